// round 9
// baseline (speedup 1.0000x reference)
#include <cuda_runtime.h>
#include <cuda_bf16.h>
#include <math.h>

// Problem constants
#define BATCH 256
#define SEQL  200
#define INF   512
#define HID   256
#define G3    768
#define BL    (BATCH*SEQL)   // 51200

// ---------------- scratch (device globals) -----------------------------------
__device__ float g_xi_f[(size_t)BL * G3];
__device__ float g_xi_r[(size_t)BL * G3];
__device__ float g_seq0[(size_t)BL * 512];
__device__ float g_seq1[(size_t)BL * 512];
__device__ float g_p[BL];
__device__ __nv_bfloat16 g_a2[(size_t)BL * 1024];      // A split: [row][hi(512)|lo(512)]
__device__ __nv_bfloat16 g_w2[2ull * G3 * 1024];       // W split per dir

// ---------------- f32x2 packed helpers ---------------------------------------
__device__ __forceinline__ void ffma2(unsigned long long& d, unsigned long long a,
                                      unsigned long long b) {
    asm("fma.rn.f32x2 %0, %1, %2, %0;" : "+l"(d) : "l"(a), "l"(b));
}
__device__ __forceinline__ float f2lo(unsigned long long v) {
    return __uint_as_float((unsigned)v);
}
__device__ __forceinline__ float f2hi(unsigned long long v) {
    return __uint_as_float((unsigned)(v >> 32));
}
__device__ __forceinline__ unsigned smem_u32(const void* p) {
    unsigned r;
    asm("{ .reg .u64 t; cvta.to.shared.u64 t, %1; cvt.u32.u64 %0, t; }"
        : "=r"(r) : "l"(p));
    return r;
}
__device__ __forceinline__ unsigned mapa_sh(unsigned addr, unsigned rank) {
    unsigned r;
    asm("mapa.shared::cluster.u32 %0, %1, %2;" : "=r"(r) : "r"(addr), "r"(rank));
    return r;
}
__device__ __forceinline__ void st_cluster_f32(unsigned addr, float v) {
    asm volatile("st.shared::cluster.f32 [%0], %1;"
                 :: "r"(addr), "f"(v) : "memory");
}
__device__ __forceinline__ void cluster_arrive() {
    asm volatile("barrier.cluster.arrive.aligned;" ::: "memory");
}
__device__ __forceinline__ void cluster_wait() {
    asm volatile("barrier.cluster.wait.aligned;" ::: "memory");
}
__device__ __forceinline__ void cluster_sync_full() {
    cluster_arrive(); cluster_wait();
}
__device__ __forceinline__ unsigned ctarank() {
    unsigned r;
    asm("mov.u32 %0, %%cluster_ctarank;" : "=r"(r));
    return r;
}
__device__ __forceinline__ float sigmoid_f(float x) {
    return __fdividef(1.f, 1.f + __expf(-x));
}
__device__ __forceinline__ float tanh_f(float x) {
    return 1.f - __fdividef(2.f, __expf(2.f * x) + 1.f);
}
__device__ __forceinline__ void cp_async16(unsigned sdst, const void* gsrc) {
    asm volatile("cp.async.cg.shared.global [%0], [%1], 16;"
                 :: "r"(sdst), "l"(gsrc) : "memory");
}
#define CP_COMMIT()  asm volatile("cp.async.commit_group;" ::: "memory")
#define CP_WAIT(n)   asm volatile("cp.async.wait_group %0;" :: "n"(n) : "memory")
#define SWZ(o) ((o) ^ (((o) >> 3) & 0x70))

// ---------------- warp-level bf16 MMA helpers ----------------------------------
__device__ __forceinline__ void ldsm_x4(unsigned* r, unsigned addr) {
    asm volatile("ldmatrix.sync.aligned.m8n8.x4.shared.b16 {%0,%1,%2,%3}, [%4];"
                 : "=r"(r[0]), "=r"(r[1]), "=r"(r[2]), "=r"(r[3]) : "r"(addr));
}
__device__ __forceinline__ void ldsm_x2(unsigned* r, unsigned addr) {
    asm volatile("ldmatrix.sync.aligned.m8n8.x2.shared.b16 {%0,%1}, [%2];"
                 : "=r"(r[0]), "=r"(r[1]) : "r"(addr));
}
__device__ __forceinline__ void mma_bf16(float* c, const unsigned* a, const unsigned* b) {
    asm volatile("mma.sync.aligned.m16n8k16.row.col.f32.bf16.bf16.f32 "
                 "{%0,%1,%2,%3}, {%4,%5,%6,%7}, {%8,%9}, {%0,%1,%2,%3};"
                 : "+f"(c[0]), "+f"(c[1]), "+f"(c[2]), "+f"(c[3])
                 : "r"(a[0]), "r"(a[1]), "r"(a[2]), "r"(a[3]),
                   "r"(b[0]), "r"(b[1]));
}

// ---------------- split-bf16 conversion: src[rows,512] -> dst[rows, hi|lo] ----
__global__ __launch_bounds__(256) void convert_split(
    const float* __restrict__ src, __nv_bfloat16* __restrict__ dst, int nelem)
{
    const int idx = (blockIdx.x * 256 + threadIdx.x) * 4;
    if (idx >= nelem) return;
    const int row = idx >> 9, col = idx & 511;
    const float4 v = *(const float4*)(src + idx);
    __nv_bfloat16 h0 = __float2bfloat16(v.x), h1 = __float2bfloat16(v.y);
    __nv_bfloat16 h2 = __float2bfloat16(v.z), h3 = __float2bfloat16(v.w);
    __nv_bfloat16 l0 = __float2bfloat16(v.x - __bfloat162float(h0));
    __nv_bfloat16 l1 = __float2bfloat16(v.y - __bfloat162float(h1));
    __nv_bfloat16 l2 = __float2bfloat16(v.z - __bfloat162float(h2));
    __nv_bfloat16 l3 = __float2bfloat16(v.w - __bfloat162float(h3));
    __nv_bfloat162* dh = (__nv_bfloat162*)(dst + (size_t)row * 1024 + col);
    __nv_bfloat162* dl = (__nv_bfloat162*)(dst + (size_t)row * 1024 + 512 + col);
    dh[0] = __nv_bfloat162(h0, h1); dh[1] = __nv_bfloat162(h2, h3);
    dl[0] = __nv_bfloat162(l0, l1); dl[1] = __nv_bfloat162(l2, l3);
}

// ---------------- HMMA GEMM: xi = A @ W^T + b ----------------------------------
// CTA 128m x 128n, 8 warps (2m x 4n), mma.m16n8k16 bf16. K_eff = 1536
// (hi*hi + lo*hi + hi*lo), chunks of 64 in SW128 smem, 3-stage cp.async ring,
// ONE syncthreads per chunk. fwd+rev fused over blockIdx.
#define GT_SMEM (3 * 32768 + 1024)
__global__ __launch_bounds__(256) void gemm_mma(
    const float* __restrict__ bf_, const float* __restrict__ br_)
{
    extern __shared__ char dsm[];
    __shared__ float sbias[128];
    const unsigned sbase = (smem_u32(dsm) + 1023u) & ~1023u;

    const int tid = threadIdx.x;
    const int wid = tid >> 5, lane = tid & 31;
    const int wm = wid >> 2, wn = wid & 3;     // 2 x 4 warp grid
    const int g = lane >> 2, tig = lane & 3;

    const int bx = blockIdx.x;
    const int m_tile = bx / 12;
    const int sub = bx - m_tile * 12;
    const int dir = sub >= 6;
    const int n0 = (dir ? sub - 6 : sub) * 128;
    const int m0 = m_tile * 128;
    float* C = dir ? g_xi_r : g_xi_f;
    const __nv_bfloat16* w2 = g_w2 + (size_t)dir * G3 * 1024;
    const float* bias = dir ? br_ : bf_;

    if (tid < 128) sbias[tid] = bias[n0 + tid];

    const int arow = wm * 64 + (lane & 15);
    const unsigned axm = (unsigned)(arow & 7) * 16u;
    const unsigned acol8 = (unsigned)(lane >> 4) * 16u;
    const int brow = wn * 32 + (lane & 7);
    const unsigned bxm = (unsigned)(lane & 7) * 16u;
    const unsigned bcol8 = (unsigned)((lane >> 3) & 1) * 16u;

    float acc[4][4][4];
#pragma unroll
    for (int mt = 0; mt < 4; mt++)
#pragma unroll
        for (int nt = 0; nt < 4; nt++)
#pragma unroll
            for (int q = 0; q < 4; q++) acc[mt][nt][q] = 0.f;

    const int lrow = tid & 127;
    const int isb = tid >> 7;
    auto load_chunk = [&](int c, int buf) {
        int acol, bcol;
        if (c < 8)       { acol = c * 64;              bcol = c * 64; }
        else if (c < 16) { acol = 512 + (c - 8) * 64;  bcol = (c - 8) * 64; }
        else             { acol = (c - 16) * 64;       bcol = 512 + (c - 16) * 64; }
        const __nv_bfloat16* src = isb
            ? (w2 + (size_t)(n0 + lrow) * 1024 + bcol)
            : (g_a2 + (size_t)(m0 + lrow) * 1024 + acol);
        const unsigned dbuf = sbase + (unsigned)buf * 32768u + (unsigned)isb * 16384u;
        const unsigned rowo = (unsigned)lrow * 128u;
#pragma unroll
        for (int q = 0; q < 8; q++)
            cp_async16(dbuf + SWZ(rowo + q * 16u), src + q * 8);
        CP_COMMIT();
    };

    load_chunk(0, 0);
    load_chunk(1, 1);

    int buf = 0;
    for (int c = 0; c < 24; c++) {
        if (c < 23) { CP_WAIT(1); } else { CP_WAIT(0); }
        __syncthreads();
        if (c + 2 < 24) {
            int nb = buf + 2; if (nb >= 3) nb -= 3;
            load_chunk(c + 2, nb);
        }

        const unsigned abuf = sbase + (unsigned)buf * 32768u;
        const unsigned bbuf = abuf + 16384u;
#pragma unroll
        for (int ks = 0; ks < 4; ks++) {
            const unsigned akc = (unsigned)(ks * 32) + acol8;
            const unsigned bkc = (unsigned)(ks * 32) + bcol8;
            unsigned af[4][4];
#pragma unroll
            for (int mt = 0; mt < 4; mt++)
                ldsm_x4(af[mt], abuf + (unsigned)(arow + mt * 16) * 128u + (akc ^ axm));
            unsigned bfr[4][2];
#pragma unroll
            for (int nt = 0; nt < 4; nt++)
                ldsm_x2(bfr[nt], bbuf + (unsigned)(brow + nt * 8) * 128u + (bkc ^ bxm));
#pragma unroll
            for (int mt = 0; mt < 4; mt++)
#pragma unroll
                for (int nt = 0; nt < 4; nt++)
                    mma_bf16(acc[mt][nt], af[mt], bfr[nt]);
        }
        buf++; if (buf >= 3) buf -= 3;
    }

#pragma unroll
    for (int mt = 0; mt < 4; mt++) {
        const int m = m0 + wm * 64 + mt * 16 + g;
#pragma unroll
        for (int nt = 0; nt < 4; nt++) {
            const int nloc = wn * 32 + nt * 8 + 2 * tig;
            const float b0 = sbias[nloc], b1 = sbias[nloc + 1];
            float2 v0, v1;
            v0.x = acc[mt][nt][0] + b0; v0.y = acc[mt][nt][1] + b1;
            v1.x = acc[mt][nt][2] + b0; v1.y = acc[mt][nt][3] + b1;
            *(float2*)(C + (size_t)m * G3 + n0 + nloc) = v0;
            *(float2*)(C + (size_t)(m + 8) * G3 + n0 + nloc) = v1;
        }
    }
}

// ---------------- cluster-persistent GRU recurrence ---------------------------
// 32 clusters x 8 CTAs (2 dir x 16 batch-groups of 16). CTA rank owns 32 h rows
// x 3 gates: ws = 96KB k-pair packed; hs single buffer [16 b][256 k] = 16KB.
// Dynamic smem 114688B -> TWO CTAs per SM: cluster-barrier stalls of one CTA
// are hidden by the other. 128 threads; warp = 4 batches x 32 h(lanes);
// f32x2 packs (even k, odd k) partial sums -> no operand-duplication movs.
#define RWS_FLOATS (3 * 128 * 64)      // 24576 floats = 98304 B
#define RHS_FLOATS (16 * 256)          // 4096 floats  = 16384 B
#define GRU_SMEM_BYTES ((RWS_FLOATS + RHS_FLOATS) * 4)   // 114688

__global__ void __launch_bounds__(128) __cluster_dims__(8, 1, 1)
gru_cluster(const float* __restrict__ whh_f, const float* __restrict__ whh_r,
            const float* __restrict__ bhh_f, const float* __restrict__ bhh_r,
            int layer)
{
    extern __shared__ float sm[];
    float* ws = sm;                    // [(g*128+kk)*64 + hl*2 + par]
    float* hs = sm + RWS_FLOATS;       // [b*256 + k]

    const unsigned rank = ctarank();
    const int cid = blockIdx.x >> 3;
    const int dir = cid >> 4;
    const int bg  = cid & 15;

    float* seq = layer ? g_seq1 : g_seq0;
    const float* xi  = dir ? g_xi_r : g_xi_f;
    const float* whh = dir ? whh_r : whh_f;
    const float* bhh = dir ? bhh_r : bhh_f;
    const int zoff = dir * HID;

    const int tid = threadIdx.x;
    const int w = tid >> 5, lane = tid & 31;
    const int bb = w * 4;                    // 4 batches per warp
    const int hglob = rank * 32 + lane;

    // ---- stage weights k-pair packed: ws[(g*128+kk)*64 + hl*2] ----
    {
        const int hl = tid & 31;
        const int kb = (tid >> 5) * 32;
        for (int g = 0; g < 3; g++) {
            const float* wrow = whh + (size_t)(g * HID + rank * 32 + hl) * HID;
#pragma unroll 4
            for (int kk = kb; kk < kb + 32; kk++) {
                float2 v = *(const float2*)(wrow + 2 * kk);
                *(float2*)&ws[(g * 128 + kk) * 64 + hl * 2] = v;
            }
        }
    }
    for (int i = tid; i < RHS_FLOATS; i += 128) hs[i] = 0.f;   // h0 = 0
    __syncthreads();
    cluster_sync_full();

    const float br = bhh[hglob], bz = bhh[HID + hglob], bn = bhh[2 * HID + hglob];
    unsigned rbase[8];
#pragma unroll
    for (unsigned r = 0; r < 8; r++) rbase[r] = mapa_sh(smem_u32(hs), r);

    // initial xi prefetch
    float xig[3][4];
#pragma unroll
    for (int j = 0; j < 4; j++) {
        const int b = bg * 16 + bb + j;
        const int t0 = dir ? (SEQL - 1) : 0;
        const float* xp = xi + ((size_t)b * SEQL + t0) * G3 + hglob;
#pragma unroll
        for (int g = 0; g < 3; g++) xig[g][j] = __ldg(xp + g * HID);
    }

    for (int s = 0; s < SEQL; s++) {
        const int t = dir ? (SEQL - 1 - s) : s;

        unsigned long long acc[3][4];
#pragma unroll
        for (int g = 0; g < 3; g++)
#pragma unroll
            for (int j = 0; j < 4; j++) acc[g][j] = 0ull;

#pragma unroll 4
        for (int kk = 0; kk < 128; kk++) {
            unsigned long long h2[4];
#pragma unroll
            for (int j = 0; j < 4; j++)
                h2[j] = *(const unsigned long long*)&hs[(bb + j) * 256 + 2 * kk];
#pragma unroll
            for (int g = 0; g < 3; g++) {
                const unsigned long long w2 =
                    *(const unsigned long long*)&ws[(g * 128 + kk) * 64 + lane * 2];
#pragma unroll
                for (int j = 0; j < 4; j++) ffma2(acc[g][j], h2[j], w2);
            }
        }

        float hp[4];
#pragma unroll
        for (int j = 0; j < 4; j++) hp[j] = hs[(bb + j) * 256 + hglob];

        cluster_arrive();   // done reading hs; wait hidden under epilogue

        float hnew[4];
#pragma unroll
        for (int j = 0; j < 4; j++) {
            const float gr = f2lo(acc[0][j]) + f2hi(acc[0][j]) + br;
            const float gz = f2lo(acc[1][j]) + f2hi(acc[1][j]) + bz;
            const float gn = f2lo(acc[2][j]) + f2hi(acc[2][j]) + bn;
            const float rg = sigmoid_f(xig[0][j] + gr);
            const float zg = sigmoid_f(xig[1][j] + gz);
            const float ng = tanh_f(xig[2][j] + rg * gn);
            hnew[j] = (1.f - zg) * ng + zg * hp[j];
            const int b = bg * 16 + bb + j;
            seq[((size_t)b * SEQL + t) * 512 + zoff + hglob] = hnew[j];
        }

        cluster_wait();     // all CTAs done reading -> safe to overwrite hs

#pragma unroll
        for (unsigned r = 0; r < 8; r++) {
#pragma unroll
            for (int j = 0; j < 4; j++)
                st_cluster_f32(rbase[r] + (unsigned)(((bb + j) * 256 + hglob) * 4),
                               hnew[j]);
        }

        cluster_arrive();   // stores released; wait hidden under xi prefetch

        if (s + 1 < SEQL) {
            const int tn_ = dir ? (SEQL - 2 - s) : (s + 1);
#pragma unroll
            for (int j = 0; j < 4; j++) {
                const int b = bg * 16 + bb + j;
                const float* xp = xi + ((size_t)b * SEQL + tn_) * G3 + hglob;
#pragma unroll
                for (int g = 0; g < 3; g++) xig[g][j] = __ldg(xp + g * HID);
            }
        }

        cluster_wait();     // h_s visible everywhere
    }
}

// ---------------- heads ------------------------------------------------------
__global__ __launch_bounds__(128) void fc_heads(
    const float* __restrict__ fc1w, const float* __restrict__ fc1b,
    const float* __restrict__ fc2w, const float* __restrict__ fc2b,
    float* __restrict__ y, float* __restrict__ y2)
{
    const int bt = blockIdx.x;
    __shared__ float row[512];
    const int tid = threadIdx.x;
    const float* src = g_seq1 + (size_t)bt * 512;
    for (int i = tid; i < 512; i += 128) row[i] = src[i];
    __syncthreads();
    const int warp = tid >> 5, lane = tid & 31;
    for (int j = warp; j < 11; j += 4) {
        const float* w = (j == 10) ? fc1w : fc2w + (size_t)j * 512;
        float s = 0.f;
#pragma unroll
        for (int i = 0; i < 16; i++) s += row[lane + 32 * i] * w[lane + 32 * i];
#pragma unroll
        for (int off = 16; off; off >>= 1) s += __shfl_xor_sync(0xffffffffu, s, off);
        if (lane == 0) {
            if (j == 10) y[bt] = s + fc1b[0];
            else         y2[(size_t)bt * 10 + j] = s + fc2b[j];
        }
    }
}

__global__ __launch_bounds__(256) void softmax_y_kernel(const float* __restrict__ y) {
    const int b = blockIdx.x;
    __shared__ float sh[256];
    const int tid = threadIdx.x;
    float v = (tid < SEQL) ? y[b * SEQL + tid] : -INFINITY;
    sh[tid] = v; __syncthreads();
    for (int s = 128; s; s >>= 1) {
        if (tid < s) sh[tid] = fmaxf(sh[tid], sh[tid + s]);
        __syncthreads();
    }
    const float mx = sh[0]; __syncthreads();
    const float e = (tid < SEQL) ? __expf(v - mx) : 0.f;
    sh[tid] = e; __syncthreads();
    for (int s = 128; s; s >>= 1) {
        if (tid < s) sh[tid] += sh[tid + s];
        __syncthreads();
    }
    const float inv = 1.f / sh[0];
    if (tid < SEQL) g_p[b * SEQL + tid] = e * inv * 0.1f;
}

__global__ __launch_bounds__(256) void softmax_y2_kernel(
    const float* __restrict__ y2, float* __restrict__ y3)
{
    const int b = blockIdx.x;
    const int tid = threadIdx.x;
    __shared__ float sh[256];
    const float* src = y2 + (size_t)b * 2000;
    float mx = -INFINITY;
    for (int i = tid; i < 2000; i += 256) mx = fmaxf(mx, src[i]);
    sh[tid] = mx; __syncthreads();
    for (int s = 128; s; s >>= 1) {
        if (tid < s) sh[tid] = fmaxf(sh[tid], sh[tid + s]);
        __syncthreads();
    }
    mx = sh[0]; __syncthreads();
    float sum = 0.f;
    for (int i = tid; i < 2000; i += 256) sum += __expf(src[i] - mx);
    sh[tid] = sum; __syncthreads();
    for (int s = 128; s; s >>= 1) {
        if (tid < s) sh[tid] += sh[tid + s];
        __syncthreads();
    }
    const float inv = 1.f / sh[0];
    for (int i = tid; i < 2000; i += 256)
        y3[(size_t)b * 2000 + i] = __expf(src[i] - mx) * inv + g_p[b * SEQL + i / 10];
}

// ---------------- driver ------------------------------------------------------
extern "C" void kernel_launch(void* const* d_in, const int* in_sizes, int n_in,
                              void* d_out, int out_size) {
    (void)in_sizes; (void)n_in; (void)out_size;
    const float* x        = (const float*)d_in[0];
    const float* w_ih_l0  = (const float*)d_in[1];
    const float* w_hh_l0  = (const float*)d_in[2];
    const float* b_ih_l0  = (const float*)d_in[3];
    const float* b_hh_l0  = (const float*)d_in[4];
    const float* w_ih_l0r = (const float*)d_in[5];
    const float* w_hh_l0r = (const float*)d_in[6];
    const float* b_ih_l0r = (const float*)d_in[7];
    const float* b_hh_l0r = (const float*)d_in[8];
    const float* w_ih_l1  = (const float*)d_in[9];
    const float* w_hh_l1  = (const float*)d_in[10];
    const float* b_ih_l1  = (const float*)d_in[11];
    const float* b_hh_l1  = (const float*)d_in[12];
    const float* w_ih_l1r = (const float*)d_in[13];
    const float* w_hh_l1r = (const float*)d_in[14];
    const float* b_ih_l1r = (const float*)d_in[15];
    const float* b_hh_l1r = (const float*)d_in[16];
    const float* fc1_w    = (const float*)d_in[17];
    const float* fc1_b    = (const float*)d_in[18];
    const float* fc2_w    = (const float*)d_in[19];
    const float* fc2_b    = (const float*)d_in[20];

    float* y  = (float*)d_out;
    float* y2 = y + BL;
    float* y3 = y2 + BL * 10;

    static int configured = 0;
    if (!configured) {
        cudaFuncSetAttribute(gru_cluster, cudaFuncAttributeMaxDynamicSharedMemorySize,
                             GRU_SMEM_BYTES);
        cudaFuncSetAttribute(gemm_mma, cudaFuncAttributeMaxDynamicSharedMemorySize,
                             GT_SMEM);
        configured = 1;
    }

    __nv_bfloat16* a2p = nullptr;
    __nv_bfloat16* w2p = nullptr;
    cudaGetSymbolAddress((void**)&a2p, g_a2);
    cudaGetSymbolAddress((void**)&w2p, g_w2);
    float* seq0p = nullptr;
    cudaGetSymbolAddress((void**)&seq0p, g_seq0);

    const int A_ELEM = BL * 512;
    const int W_ELEM = G3 * 512;

    // ---- layer 0 ----
    convert_split<<<A_ELEM / 1024, 256>>>(x, a2p, A_ELEM);
    convert_split<<<W_ELEM / 1024, 256>>>(w_ih_l0,  w2p,                     W_ELEM);
    convert_split<<<W_ELEM / 1024, 256>>>(w_ih_l0r, w2p + (size_t)G3 * 1024, W_ELEM);
    gemm_mma<<<(BL / 128) * 12, 256, GT_SMEM>>>(b_ih_l0, b_ih_l0r);
    gru_cluster<<<256, 128, GRU_SMEM_BYTES>>>(w_hh_l0, w_hh_l0r, b_hh_l0, b_hh_l0r, 0);

    // ---- layer 1 ----
    convert_split<<<A_ELEM / 1024, 256>>>(seq0p, a2p, A_ELEM);
    convert_split<<<W_ELEM / 1024, 256>>>(w_ih_l1,  w2p,                     W_ELEM);
    convert_split<<<W_ELEM / 1024, 256>>>(w_ih_l1r, w2p + (size_t)G3 * 1024, W_ELEM);
    gemm_mma<<<(BL / 128) * 12, 256, GT_SMEM>>>(b_ih_l1, b_ih_l1r);
    gru_cluster<<<256, 128, GRU_SMEM_BYTES>>>(w_hh_l1, w_hh_l1r, b_hh_l1, b_hh_l1r, 1);

    // ---- heads ----
    fc_heads<<<BL, 128>>>(fc1_w, fc1_b, fc2_w, fc2_b, y, y2);
    softmax_y_kernel<<<BATCH, 256>>>(y);
    softmax_y2_kernel<<<BATCH, 256>>>(y2, y3);
}

// round 10
// speedup vs baseline: 2.3107x; 2.3107x over previous
#include <cuda_runtime.h>
#include <cuda_bf16.h>
#include <math.h>

// Problem constants
#define BATCH 256
#define SEQL  200
#define INF   512
#define HID   256
#define G3    768
#define BL    (BATCH*SEQL)   // 51200

// ---------------- scratch (device globals) -----------------------------------
__device__ float g_xi_f[(size_t)BL * G3];
__device__ float g_xi_r[(size_t)BL * G3];
__device__ float g_seq0[(size_t)BL * 512];
__device__ float g_seq1[(size_t)BL * 512];
__device__ float g_p[BL];
__device__ __nv_bfloat16 g_a2[(size_t)BL * 1024];      // A split: [row][hi(512)|lo(512)]
__device__ __nv_bfloat16 g_w2[2ull * G3 * 1024];       // W split per dir

// ---------------- helpers -----------------------------------------------------
__device__ __forceinline__ unsigned smem_u32(const void* p) {
    unsigned r;
    asm("{ .reg .u64 t; cvta.to.shared.u64 t, %1; cvt.u32.u64 %0, t; }"
        : "=r"(r) : "l"(p));
    return r;
}
__device__ __forceinline__ unsigned mapa_sh(unsigned addr, unsigned rank) {
    unsigned r;
    asm("mapa.shared::cluster.u32 %0, %1, %2;" : "=r"(r) : "r"(addr), "r"(rank));
    return r;
}
__device__ __forceinline__ void st_cluster_u32(unsigned addr, unsigned v) {
    asm volatile("st.shared::cluster.u32 [%0], %1;" :: "r"(addr), "r"(v) : "memory");
}
__device__ __forceinline__ void cluster_arrive() {
    asm volatile("barrier.cluster.arrive.aligned;" ::: "memory");
}
__device__ __forceinline__ void cluster_wait() {
    asm volatile("barrier.cluster.wait.aligned;" ::: "memory");
}
__device__ __forceinline__ void cluster_sync_full() {
    cluster_arrive(); cluster_wait();
}
__device__ __forceinline__ unsigned ctarank() {
    unsigned r;
    asm("mov.u32 %0, %%cluster_ctarank;" : "=r"(r));
    return r;
}
__device__ __forceinline__ float sigmoid_f(float x) {
    return __fdividef(1.f, 1.f + __expf(-x));
}
__device__ __forceinline__ float tanh_f(float x) {
    return 1.f - __fdividef(2.f, __expf(2.f * x) + 1.f);
}
__device__ __forceinline__ void cp_async16(unsigned sdst, const void* gsrc) {
    asm volatile("cp.async.cg.shared.global [%0], [%1], 16;"
                 :: "r"(sdst), "l"(gsrc) : "memory");
}
#define CP_COMMIT()  asm volatile("cp.async.commit_group;" ::: "memory")
#define CP_WAIT(n)   asm volatile("cp.async.wait_group %0;" :: "n"(n) : "memory")
#define SWZ(o) ((o) ^ (((o) >> 3) & 0x70))

__device__ __forceinline__ void ldsm_x4(unsigned* r, unsigned addr) {
    asm volatile("ldmatrix.sync.aligned.m8n8.x4.shared.b16 {%0,%1,%2,%3}, [%4];"
                 : "=r"(r[0]), "=r"(r[1]), "=r"(r[2]), "=r"(r[3]) : "r"(addr));
}
__device__ __forceinline__ void ldsm_x2(unsigned* r, unsigned addr) {
    asm volatile("ldmatrix.sync.aligned.m8n8.x2.shared.b16 {%0,%1}, [%2];"
                 : "=r"(r[0]), "=r"(r[1]) : "r"(addr));
}
__device__ __forceinline__ void mma_bf16(float* c, const unsigned* a, const unsigned* b) {
    asm volatile("mma.sync.aligned.m16n8k16.row.col.f32.bf16.bf16.f32 "
                 "{%0,%1,%2,%3}, {%4,%5,%6,%7}, {%8,%9}, {%0,%1,%2,%3};"
                 : "+f"(c[0]), "+f"(c[1]), "+f"(c[2]), "+f"(c[3])
                 : "r"(a[0]), "r"(a[1]), "r"(a[2]), "r"(a[3]),
                   "r"(b[0]), "r"(b[1]));
}
__device__ __forceinline__ unsigned pack_bf16(float a, float b) {
    __nv_bfloat162 t = __floats2bfloat162_rn(a, b);
    return *(unsigned*)&t;
}

// ---------------- split-bf16 conversion: src[rows,512] -> dst[rows, hi|lo] ----
__global__ __launch_bounds__(256) void convert_split(
    const float* __restrict__ src, __nv_bfloat16* __restrict__ dst, int nelem)
{
    const int idx = (blockIdx.x * 256 + threadIdx.x) * 4;
    if (idx >= nelem) return;
    const int row = idx >> 9, col = idx & 511;
    const float4 v = *(const float4*)(src + idx);
    __nv_bfloat16 h0 = __float2bfloat16(v.x), h1 = __float2bfloat16(v.y);
    __nv_bfloat16 h2 = __float2bfloat16(v.z), h3 = __float2bfloat16(v.w);
    __nv_bfloat16 l0 = __float2bfloat16(v.x - __bfloat162float(h0));
    __nv_bfloat16 l1 = __float2bfloat16(v.y - __bfloat162float(h1));
    __nv_bfloat16 l2 = __float2bfloat16(v.z - __bfloat162float(h2));
    __nv_bfloat16 l3 = __float2bfloat16(v.w - __bfloat162float(h3));
    __nv_bfloat162* dh = (__nv_bfloat162*)(dst + (size_t)row * 1024 + col);
    __nv_bfloat162* dl = (__nv_bfloat162*)(dst + (size_t)row * 1024 + 512 + col);
    dh[0] = __nv_bfloat162(h0, h1); dh[1] = __nv_bfloat162(h2, h3);
    dl[0] = __nv_bfloat162(l0, l1); dl[1] = __nv_bfloat162(l2, l3);
}

// ---------------- HMMA GEMM: xi = A @ W^T + b (R8 proven config) ---------------
#define GT_SMEM (2 * 32768 + 1024)
__global__ __launch_bounds__(256) void gemm_mma(
    const float* __restrict__ bf_, const float* __restrict__ br_)
{
    extern __shared__ char dsm[];
    __shared__ float sbias[128];
    const unsigned sbase = (smem_u32(dsm) + 1023u) & ~1023u;

    const int tid = threadIdx.x;
    const int wid = tid >> 5, lane = tid & 31;
    const int wm = wid >> 2, wn = wid & 3;
    const int g = lane >> 2, tig = lane & 3;

    const int bx = blockIdx.x;
    const int m_tile = bx / 12;
    const int sub = bx - m_tile * 12;
    const int dir = sub >= 6;
    const int n0 = (dir ? sub - 6 : sub) * 128;
    const int m0 = m_tile * 128;
    float* C = dir ? g_xi_r : g_xi_f;
    const __nv_bfloat16* w2 = g_w2 + (size_t)dir * G3 * 1024;
    const float* bias = dir ? br_ : bf_;

    if (tid < 128) sbias[tid] = bias[n0 + tid];

    const int arow = wm * 64 + (lane & 15);
    const unsigned axm = (unsigned)(arow & 7) * 16u;
    const unsigned acol8 = (unsigned)(lane >> 4) * 16u;
    const int brow = wn * 32 + (lane & 7);
    const unsigned bxm = (unsigned)(lane & 7) * 16u;
    const unsigned bcol8 = (unsigned)((lane >> 3) & 1) * 16u;

    float acc[4][4][4];
#pragma unroll
    for (int mt = 0; mt < 4; mt++)
#pragma unroll
        for (int nt = 0; nt < 4; nt++)
#pragma unroll
            for (int q = 0; q < 4; q++) acc[mt][nt][q] = 0.f;

    const int lrow = tid & 127;
    const int isb = tid >> 7;
    auto load_chunk = [&](int c, int buf) {
        int acol, bcol;
        if (c < 8)       { acol = c * 64;              bcol = c * 64; }
        else if (c < 16) { acol = 512 + (c - 8) * 64;  bcol = (c - 8) * 64; }
        else             { acol = (c - 16) * 64;       bcol = 512 + (c - 16) * 64; }
        const __nv_bfloat16* src = isb
            ? (w2 + (size_t)(n0 + lrow) * 1024 + bcol)
            : (g_a2 + (size_t)(m0 + lrow) * 1024 + acol);
        const unsigned dbuf = sbase + (unsigned)buf * 32768u + (unsigned)isb * 16384u;
        const unsigned rowo = (unsigned)lrow * 128u;
#pragma unroll
        for (int q = 0; q < 8; q++)
            cp_async16(dbuf + SWZ(rowo + q * 16u), src + q * 8);
        CP_COMMIT();
    };

    load_chunk(0, 0);

    for (int c = 0; c < 24; c++) {
        const int buf = c & 1;
        if (c < 23) { load_chunk(c + 1, (c + 1) & 1); CP_WAIT(1); }
        else        { CP_WAIT(0); }
        __syncthreads();

        const unsigned abuf = sbase + (unsigned)buf * 32768u;
        const unsigned bbuf = abuf + 16384u;
#pragma unroll
        for (int ks = 0; ks < 4; ks++) {
            const unsigned akc = (unsigned)(ks * 32) + acol8;
            const unsigned bkc = (unsigned)(ks * 32) + bcol8;
            unsigned af[4][4];
#pragma unroll
            for (int mt = 0; mt < 4; mt++)
                ldsm_x4(af[mt], abuf + (unsigned)(arow + mt * 16) * 128u + (akc ^ axm));
            unsigned bfr[4][2];
#pragma unroll
            for (int nt = 0; nt < 4; nt++)
                ldsm_x2(bfr[nt], bbuf + (unsigned)(brow + nt * 8) * 128u + (bkc ^ bxm));
#pragma unroll
            for (int mt = 0; mt < 4; mt++)
#pragma unroll
                for (int nt = 0; nt < 4; nt++)
                    mma_bf16(acc[mt][nt], af[mt], bfr[nt]);
        }
        __syncthreads();
    }

#pragma unroll
    for (int mt = 0; mt < 4; mt++) {
        const int m = m0 + wm * 64 + mt * 16 + g;
#pragma unroll
        for (int nt = 0; nt < 4; nt++) {
            const int nloc = wn * 32 + nt * 8 + 2 * tig;
            const float b0 = sbias[nloc], b1 = sbias[nloc + 1];
            float2 v0, v1;
            v0.x = acc[mt][nt][0] + b0; v0.y = acc[mt][nt][1] + b1;
            v1.x = acc[mt][nt][2] + b0; v1.y = acc[mt][nt][3] + b1;
            *(float2*)(C + (size_t)m * G3 + n0 + nloc) = v0;
            *(float2*)(C + (size_t)(m + 8) * G3 + n0 + nloc) = v1;
        }
    }
}

// ---------------- cluster-persistent GRU recurrence (tensor-core step) --------
// 32 clusters x 4 CTAs (R6/R8 shell: 256 thr, proven placement). CTA rank owns
// 64 h x 3 gates. Per step: gh = h @ Whh^T as split-bf16 HMMA, M=16(b),
// N=192(g*64+h), K=256. Whh resident in SMEM as bf16 hi/lo (192KB). h passed
// between steps as bf16 (hi,lo) pairs written via DSMEM directly into each
// rank's ldmatrix-ready Ah/Al buffers (16 rows x 512B, row-xor swizzle).
#define RW_HI   0u
#define RW_LO   98304u
#define RA_HI   196608u
#define RA_LO   204800u
#define GRU_SMEM_BYTES 212992u

__global__ void __launch_bounds__(256, 1) __cluster_dims__(4, 1, 1)
gru_cluster(const float* __restrict__ whh_f, const float* __restrict__ whh_r,
            const float* __restrict__ bhh_f, const float* __restrict__ bhh_r,
            int layer)
{
    extern __shared__ char rsm[];
    const unsigned sb = smem_u32(rsm);

    const unsigned rank = ctarank();
    const int cid = blockIdx.x >> 2;
    const int dir = cid >> 4;
    const int bg  = cid & 15;

    float* seq = layer ? g_seq1 : g_seq0;
    const float* xi  = dir ? g_xi_r : g_xi_f;
    const float* whh = dir ? whh_r : whh_f;
    const float* bhh = dir ? bhh_r : bhh_f;
    const int zoff = dir * HID;

    const int tid = threadIdx.x;
    const int w = tid >> 5, lane = tid & 31;

    // ---- stage Whh -> SMEM bf16 hi/lo, rows n = g*64+hl, 512B, row-xor swizzle
    if (tid < 192) {
        const int n = tid;
        const int gg = n >> 6, hl = n & 63;
        const float* wrow = whh + (size_t)(gg * HID + rank * 64 + hl) * HID;
        const unsigned rbase = sb + (unsigned)n * 512u;
        const unsigned xm = (unsigned)(n & 7) * 16u;
#pragma unroll 4
        for (int kk = 0; kk < 128; kk++) {
            const float2 v = *(const float2*)(wrow + 2 * kk);
            const float h0f = __bfloat162float(__float2bfloat16(v.x));
            const float h1f = __bfloat162float(__float2bfloat16(v.y));
            const unsigned off = ((unsigned)(kk * 4)) ^ xm;
            *(unsigned*)(rsm + (rbase - sb) + RW_HI + off) = pack_bf16(v.x, v.y);
            // overwrite with proper hi/lo: hi first
            *(unsigned*)(rsm + (rbase - sb) + RW_HI + off) =
                pack_bf16(v.x, v.y);  // pack rounds to nearest bf16 = hi
            *(unsigned*)(rsm + (rbase - sb) + RW_LO + off) =
                pack_bf16(v.x - h0f, v.y - h1f);
        }
    }
    // zero Ah/Al (h0 = 0)
    for (unsigned i = tid; i < 4096; i += 256)
        *(unsigned*)(rsm + RA_HI + i * 4) = 0u;
    __syncthreads();
    cluster_sync_full();

    // ---- per-lane geometry ----
    const int hl2 = w * 8 + (lane & 3) * 2;          // local h pair base (0..62)
    const int hg0 = rank * 64 + hl2;                 // global h (even)
    const int b0 = lane >> 2;                        // batches b0, b0+8
    const float2 br2 = *(const float2*)(bhh + hg0);
    const float2 bz2 = *(const float2*)(bhh + HID + hg0);
    const float2 bn2 = *(const float2*)(bhh + 2 * HID + hg0);

    // ldmatrix addressing constants
    const unsigned arow_off = (unsigned)(lane & 15) * 512u;
    const unsigned axor = (unsigned)((lane & 15) & 7) * 16u;
    const unsigned acol = (unsigned)(lane >> 4) * 16u;
    const unsigned bxor = (unsigned)(lane & 7) * 16u;
    const unsigned bcol = (unsigned)(lane >> 3) * 16u;   // x4 B: 2 ksteps
    unsigned wrow_off[3];
#pragma unroll
    for (int gg = 0; gg < 3; gg++)
        wrow_off[gg] = (unsigned)((gg * 64 + w * 8 + (lane & 7)) * 512);

    // DSMEM destination offsets (same in every rank's smem)
    const unsigned xw0 = (unsigned)(b0 & 7) * 16u;
    const unsigned xw1 = (unsigned)((b0 + 8) & 7) * 16u;
    const unsigned offA0 = RA_HI + (unsigned)b0 * 512u + (((unsigned)(2 * hg0)) ^ xw0);
    const unsigned offA1 = RA_HI + (unsigned)(b0 + 8) * 512u + (((unsigned)(2 * hg0)) ^ xw1);
    const unsigned offL0 = offA0 + (RA_LO - RA_HI);
    const unsigned offL1 = offA1 + (RA_LO - RA_HI);
    unsigned rmap[4];
#pragma unroll
    for (unsigned r = 0; r < 4; r++) rmap[r] = mapa_sh(sb, r);

    // initial xi prefetch (pairs)
    float2 xig[3][2];   // [gate][bi] for h pair
    float2 xig2[3][2];
    {
        const int t0 = dir ? (SEQL - 1) : 0;
        const float* xp0 = xi + ((size_t)(bg * 16 + b0) * SEQL + t0) * G3 + hg0;
        const float* xp1 = xi + ((size_t)(bg * 16 + b0 + 8) * SEQL + t0) * G3 + hg0;
#pragma unroll
        for (int gg = 0; gg < 3; gg++) {
            xig[gg][0] = *(const float2*)(xp0 + gg * HID);
            xig[gg][1] = *(const float2*)(xp1 + gg * HID);
        }
        (void)xig2;
    }

    for (int s = 0; s < SEQL; s++) {
        const int t = dir ? (SEQL - 1 - s) : s;

        float acc[3][4];
#pragma unroll
        for (int gg = 0; gg < 3; gg++)
#pragma unroll
            for (int q = 0; q < 4; q++) acc[gg][q] = 0.f;

        // ---- 3-term split-bf16 HMMA: hh, lh, hl ----
#pragma unroll
        for (int term = 0; term < 3; term++) {
            const unsigned Ab = sb + ((term == 1) ? RA_LO : RA_HI);
            const unsigned Wb = sb + ((term == 2) ? RW_LO : RW_HI);
#pragma unroll
            for (int ks2 = 0; ks2 < 8; ks2++) {
                const unsigned k0b = (unsigned)(ks2 * 64);   // bytes: 32 k elems
                unsigned af0[4], af1[4];
                ldsm_x4(af0, Ab + arow_off + ((k0b + acol) ^ axor));
                ldsm_x4(af1, Ab + arow_off + ((k0b + 32u + acol) ^ axor));
#pragma unroll
                for (int gg = 0; gg < 3; gg++) {
                    unsigned bfr[4];
                    ldsm_x4(bfr, Wb + wrow_off[gg] + ((k0b + bcol) ^ bxor));
                    mma_bf16(acc[gg], af0, bfr);
                    mma_bf16(acc[gg], af1, bfr + 2);
                }
            }
        }

        // ---- h_prev from Ah/Al (last reads of shared h-state) ----
        float hp[2][2];
        {
            const __nv_bfloat162 h0w = *(const __nv_bfloat162*)(rsm + offA0);
            const __nv_bfloat162 l0w = *(const __nv_bfloat162*)(rsm + offL0);
            const __nv_bfloat162 h1w = *(const __nv_bfloat162*)(rsm + offA1);
            const __nv_bfloat162 l1w = *(const __nv_bfloat162*)(rsm + offL1);
            hp[0][0] = __bfloat162float(h0w.x) + __bfloat162float(l0w.x);
            hp[0][1] = __bfloat162float(h0w.y) + __bfloat162float(l0w.y);
            hp[1][0] = __bfloat162float(h1w.x) + __bfloat162float(l1w.x);
            hp[1][1] = __bfloat162float(h1w.y) + __bfloat162float(l1w.y);
        }

        cluster_arrive();   // this CTA done reading h-state

        // ---- epilogue: gates; acc rows = (b0 | b0+8), cols = (hg0 | hg0+1) ----
        float hnew[2][2];
#pragma unroll
        for (int bi = 0; bi < 2; bi++) {
#pragma unroll
            for (int hj = 0; hj < 2; hj++) {
                const int q = bi * 2 + hj;
                const float gr = acc[0][q] + (hj ? br2.y : br2.x);
                const float gz = acc[1][q] + (hj ? bz2.y : bz2.x);
                const float gn = acc[2][q] + (hj ? bn2.y : bn2.x);
                const float xr = hj ? xig[0][bi].y : xig[0][bi].x;
                const float xz = hj ? xig[1][bi].y : xig[1][bi].x;
                const float xn = hj ? xig[2][bi].y : xig[2][bi].x;
                const float rg = sigmoid_f(xr + gr);
                const float zg = sigmoid_f(xz + gz);
                const float ng = tanh_f(xn + rg * gn);
                hnew[bi][hj] = (1.f - zg) * ng + zg * hp[bi][hj];
            }
            const int b = bg * 16 + b0 + bi * 8;
            *(float2*)(seq + ((size_t)b * SEQL + t) * 512 + zoff + hg0) =
                make_float2(hnew[bi][0], hnew[bi][1]);
        }

        // pack hi/lo words
        const float h00 = __bfloat162float(__float2bfloat16(hnew[0][0]));
        const float h01 = __bfloat162float(__float2bfloat16(hnew[0][1]));
        const float h10 = __bfloat162float(__float2bfloat16(hnew[1][0]));
        const float h11 = __bfloat162float(__float2bfloat16(hnew[1][1]));
        const unsigned wh0 = pack_bf16(hnew[0][0], hnew[0][1]);
        const unsigned wl0 = pack_bf16(hnew[0][0] - h00, hnew[0][1] - h01);
        const unsigned wh1 = pack_bf16(hnew[1][0], hnew[1][1]);
        const unsigned wl1 = pack_bf16(hnew[1][0] - h10, hnew[1][1] - h11);

        cluster_wait();     // all CTAs done reading -> safe to overwrite

#pragma unroll
        for (unsigned r = 0; r < 4; r++) {
            st_cluster_u32(rmap[r] + offA0, wh0);
            st_cluster_u32(rmap[r] + offL0, wl0);
            st_cluster_u32(rmap[r] + offA1, wh1);
            st_cluster_u32(rmap[r] + offL1, wl1);
        }

        cluster_arrive();   // stores released; wait hidden under xi prefetch

        if (s + 1 < SEQL) {
            const int tn_ = dir ? (SEQL - 2 - s) : (s + 1);
            const float* xp0 = xi + ((size_t)(bg * 16 + b0) * SEQL + tn_) * G3 + hg0;
            const float* xp1 = xi + ((size_t)(bg * 16 + b0 + 8) * SEQL + tn_) * G3 + hg0;
#pragma unroll
            for (int gg = 0; gg < 3; gg++) {
                xig[gg][0] = *(const float2*)(xp0 + gg * HID);
                xig[gg][1] = *(const float2*)(xp1 + gg * HID);
            }
        }

        cluster_wait();     // h_s visible everywhere
    }
}

// ---------------- heads ------------------------------------------------------
__global__ __launch_bounds__(128) void fc_heads(
    const float* __restrict__ fc1w, const float* __restrict__ fc1b,
    const float* __restrict__ fc2w, const float* __restrict__ fc2b,
    float* __restrict__ y, float* __restrict__ y2)
{
    const int bt = blockIdx.x;
    __shared__ float row[512];
    const int tid = threadIdx.x;
    const float* src = g_seq1 + (size_t)bt * 512;
    for (int i = tid; i < 512; i += 128) row[i] = src[i];
    __syncthreads();
    const int warp = tid >> 5, lane = tid & 31;
    for (int j = warp; j < 11; j += 4) {
        const float* w = (j == 10) ? fc1w : fc2w + (size_t)j * 512;
        float s = 0.f;
#pragma unroll
        for (int i = 0; i < 16; i++) s += row[lane + 32 * i] * w[lane + 32 * i];
#pragma unroll
        for (int off = 16; off; off >>= 1) s += __shfl_xor_sync(0xffffffffu, s, off);
        if (lane == 0) {
            if (j == 10) y[bt] = s + fc1b[0];
            else         y2[(size_t)bt * 10 + j] = s + fc2b[j];
        }
    }
}

__global__ __launch_bounds__(256) void softmax_y_kernel(const float* __restrict__ y) {
    const int b = blockIdx.x;
    __shared__ float sh[256];
    const int tid = threadIdx.x;
    float v = (tid < SEQL) ? y[b * SEQL + tid] : -INFINITY;
    sh[tid] = v; __syncthreads();
    for (int s = 128; s; s >>= 1) {
        if (tid < s) sh[tid] = fmaxf(sh[tid], sh[tid + s]);
        __syncthreads();
    }
    const float mx = sh[0]; __syncthreads();
    const float e = (tid < SEQL) ? __expf(v - mx) : 0.f;
    sh[tid] = e; __syncthreads();
    for (int s = 128; s; s >>= 1) {
        if (tid < s) sh[tid] += sh[tid + s];
        __syncthreads();
    }
    const float inv = 1.f / sh[0];
    if (tid < SEQL) g_p[b * SEQL + tid] = e * inv * 0.1f;
}

__global__ __launch_bounds__(256) void softmax_y2_kernel(
    const float* __restrict__ y2, float* __restrict__ y3)
{
    const int b = blockIdx.x;
    const int tid = threadIdx.x;
    __shared__ float sh[256];
    const float* src = y2 + (size_t)b * 2000;
    float mx = -INFINITY;
    for (int i = tid; i < 2000; i += 256) mx = fmaxf(mx, src[i]);
    sh[tid] = mx; __syncthreads();
    for (int s = 128; s; s >>= 1) {
        if (tid < s) sh[tid] = fmaxf(sh[tid], sh[tid + s]);
        __syncthreads();
    }
    mx = sh[0]; __syncthreads();
    float sum = 0.f;
    for (int i = tid; i < 2000; i += 256) sum += __expf(src[i] - mx);
    sh[tid] = sum; __syncthreads();
    for (int s = 128; s; s >>= 1) {
        if (tid < s) sh[tid] += sh[tid + s];
        __syncthreads();
    }
    const float inv = 1.f / sh[0];
    for (int i = tid; i < 2000; i += 256)
        y3[(size_t)b * 2000 + i] = __expf(src[i] - mx) * inv + g_p[b * SEQL + i / 10];
}

// ---------------- driver ------------------------------------------------------
extern "C" void kernel_launch(void* const* d_in, const int* in_sizes, int n_in,
                              void* d_out, int out_size) {
    (void)in_sizes; (void)n_in; (void)out_size;
    const float* x        = (const float*)d_in[0];
    const float* w_ih_l0  = (const float*)d_in[1];
    const float* w_hh_l0  = (const float*)d_in[2];
    const float* b_ih_l0  = (const float*)d_in[3];
    const float* b_hh_l0  = (const float*)d_in[4];
    const float* w_ih_l0r = (const float*)d_in[5];
    const float* w_hh_l0r = (const float*)d_in[6];
    const float* b_ih_l0r = (const float*)d_in[7];
    const float* b_hh_l0r = (const float*)d_in[8];
    const float* w_ih_l1  = (const float*)d_in[9];
    const float* w_hh_l1  = (const float*)d_in[10];
    const float* b_ih_l1  = (const float*)d_in[11];
    const float* b_hh_l1  = (const float*)d_in[12];
    const float* w_ih_l1r = (const float*)d_in[13];
    const float* w_hh_l1r = (const float*)d_in[14];
    const float* b_ih_l1r = (const float*)d_in[15];
    const float* b_hh_l1r = (const float*)d_in[16];
    const float* fc1_w    = (const float*)d_in[17];
    const float* fc1_b    = (const float*)d_in[18];
    const float* fc2_w    = (const float*)d_in[19];
    const float* fc2_b    = (const float*)d_in[20];

    float* y  = (float*)d_out;
    float* y2 = y + BL;
    float* y3 = y2 + BL * 10;

    static int configured = 0;
    if (!configured) {
        cudaFuncSetAttribute(gru_cluster, cudaFuncAttributeMaxDynamicSharedMemorySize,
                             GRU_SMEM_BYTES);
        cudaFuncSetAttribute(gemm_mma, cudaFuncAttributeMaxDynamicSharedMemorySize,
                             GT_SMEM);
        configured = 1;
    }

    __nv_bfloat16* a2p = nullptr;
    __nv_bfloat16* w2p = nullptr;
    cudaGetSymbolAddress((void**)&a2p, g_a2);
    cudaGetSymbolAddress((void**)&w2p, g_w2);
    float* seq0p = nullptr;
    cudaGetSymbolAddress((void**)&seq0p, g_seq0);

    const int A_ELEM = BL * 512;
    const int W_ELEM = G3 * 512;

    // ---- layer 0 ----
    convert_split<<<A_ELEM / 1024, 256>>>(x, a2p, A_ELEM);
    convert_split<<<W_ELEM / 1024, 256>>>(w_ih_l0,  w2p,                     W_ELEM);
    convert_split<<<W_ELEM / 1024, 256>>>(w_ih_l0r, w2p + (size_t)G3 * 1024, W_ELEM);
    gemm_mma<<<(BL / 128) * 12, 256, GT_SMEM>>>(b_ih_l0, b_ih_l0r);
    gru_cluster<<<128, 256, GRU_SMEM_BYTES>>>(w_hh_l0, w_hh_l0r, b_hh_l0, b_hh_l0r, 0);

    // ---- layer 1 ----
    convert_split<<<A_ELEM / 1024, 256>>>(seq0p, a2p, A_ELEM);
    convert_split<<<W_ELEM / 1024, 256>>>(w_ih_l1,  w2p,                     W_ELEM);
    convert_split<<<W_ELEM / 1024, 256>>>(w_ih_l1r, w2p + (size_t)G3 * 1024, W_ELEM);
    gemm_mma<<<(BL / 128) * 12, 256, GT_SMEM>>>(b_ih_l1, b_ih_l1r);
    gru_cluster<<<128, 256, GRU_SMEM_BYTES>>>(w_hh_l1, w_hh_l1r, b_hh_l1, b_hh_l1r, 1);

    // ---- heads ----
    fc_heads<<<BL, 128>>>(fc1_w, fc1_b, fc2_w, fc2_b, y, y2);
    softmax_y_kernel<<<BATCH, 256>>>(y);
    softmax_y2_kernel<<<BATCH, 256>>>(y2, y3);
}

// round 11
// speedup vs baseline: 2.3785x; 1.0293x over previous
#include <cuda_runtime.h>
#include <cuda_bf16.h>
#include <math.h>

// Problem constants
#define BATCH 256
#define SEQL  200
#define INF   512
#define HID   256
#define G3    768
#define BL    (BATCH*SEQL)   // 51200

// ---------------- scratch (device globals) -----------------------------------
__device__ float g_xi_f[(size_t)BL * G3];
__device__ float g_xi_r[(size_t)BL * G3];
__device__ float g_seq1[(size_t)BL * 512];
__device__ float g_p[BL];
__device__ __nv_bfloat16 g_a2[(size_t)BL * 1024];      // A split: [row][hi(512)|lo(512)]
__device__ __nv_bfloat16 g_w2[2ull * G3 * 1024];       // W split per dir

// ---------------- helpers -----------------------------------------------------
__device__ __forceinline__ unsigned smem_u32(const void* p) {
    unsigned r;
    asm("{ .reg .u64 t; cvta.to.shared.u64 t, %1; cvt.u32.u64 %0, t; }"
        : "=r"(r) : "l"(p));
    return r;
}
__device__ __forceinline__ unsigned mapa_sh(unsigned addr, unsigned rank) {
    unsigned r;
    asm("mapa.shared::cluster.u32 %0, %1, %2;" : "=r"(r) : "r"(addr), "r"(rank));
    return r;
}
__device__ __forceinline__ void st_cluster_u32(unsigned addr, unsigned v) {
    asm volatile("st.shared::cluster.u32 [%0], %1;" :: "r"(addr), "r"(v) : "memory");
}
__device__ __forceinline__ void cluster_arrive() {
    asm volatile("barrier.cluster.arrive.aligned;" ::: "memory");
}
__device__ __forceinline__ void cluster_wait() {
    asm volatile("barrier.cluster.wait.aligned;" ::: "memory");
}
__device__ __forceinline__ void cluster_sync_full() {
    cluster_arrive(); cluster_wait();
}
__device__ __forceinline__ unsigned ctarank() {
    unsigned r;
    asm("mov.u32 %0, %%cluster_ctarank;" : "=r"(r));
    return r;
}
__device__ __forceinline__ float sigmoid_f(float x) {
    return __fdividef(1.f, 1.f + __expf(-x));
}
__device__ __forceinline__ float tanh_f(float x) {
    return 1.f - __fdividef(2.f, __expf(2.f * x) + 1.f);
}
__device__ __forceinline__ void cp_async16(unsigned sdst, const void* gsrc) {
    asm volatile("cp.async.cg.shared.global [%0], [%1], 16;"
                 :: "r"(sdst), "l"(gsrc) : "memory");
}
#define CP_COMMIT()  asm volatile("cp.async.commit_group;" ::: "memory")
#define CP_WAIT(n)   asm volatile("cp.async.wait_group %0;" :: "n"(n) : "memory")
#define SWZ(o) ((o) ^ (((o) >> 3) & 0x70))

__device__ __forceinline__ void ldsm_x4(unsigned* r, unsigned addr) {
    asm volatile("ldmatrix.sync.aligned.m8n8.x4.shared.b16 {%0,%1,%2,%3}, [%4];"
                 : "=r"(r[0]), "=r"(r[1]), "=r"(r[2]), "=r"(r[3]) : "r"(addr));
}
__device__ __forceinline__ void ldsm_x2(unsigned* r, unsigned addr) {
    asm volatile("ldmatrix.sync.aligned.m8n8.x2.shared.b16 {%0,%1}, [%2];"
                 : "=r"(r[0]), "=r"(r[1]) : "r"(addr));
}
__device__ __forceinline__ void mma_bf16(float* c, const unsigned* a, const unsigned* b) {
    asm volatile("mma.sync.aligned.m16n8k16.row.col.f32.bf16.bf16.f32 "
                 "{%0,%1,%2,%3}, {%4,%5,%6,%7}, {%8,%9}, {%0,%1,%2,%3};"
                 : "+f"(c[0]), "+f"(c[1]), "+f"(c[2]), "+f"(c[3])
                 : "r"(a[0]), "r"(a[1]), "r"(a[2]), "r"(a[3]),
                   "r"(b[0]), "r"(b[1]));
}
__device__ __forceinline__ unsigned pack_bf16(float a, float b) {
    __nv_bfloat162 t = __floats2bfloat162_rn(a, b);
    return *(unsigned*)&t;
}

// ---------------- split-bf16 conversion: src[rows,512] -> dst[rows, hi|lo] ----
__global__ __launch_bounds__(256) void convert_split(
    const float* __restrict__ src, __nv_bfloat16* __restrict__ dst, int nelem)
{
    const int idx = (blockIdx.x * 256 + threadIdx.x) * 4;
    if (idx >= nelem) return;
    const int row = idx >> 9, col = idx & 511;
    const float4 v = *(const float4*)(src + idx);
    __nv_bfloat16 h0 = __float2bfloat16(v.x), h1 = __float2bfloat16(v.y);
    __nv_bfloat16 h2 = __float2bfloat16(v.z), h3 = __float2bfloat16(v.w);
    __nv_bfloat16 l0 = __float2bfloat16(v.x - __bfloat162float(h0));
    __nv_bfloat16 l1 = __float2bfloat16(v.y - __bfloat162float(h1));
    __nv_bfloat16 l2 = __float2bfloat16(v.z - __bfloat162float(h2));
    __nv_bfloat16 l3 = __float2bfloat16(v.w - __bfloat162float(h3));
    __nv_bfloat162* dh = (__nv_bfloat162*)(dst + (size_t)row * 1024 + col);
    __nv_bfloat162* dl = (__nv_bfloat162*)(dst + (size_t)row * 1024 + 512 + col);
    dh[0] = __nv_bfloat162(h0, h1); dh[1] = __nv_bfloat162(h2, h3);
    dl[0] = __nv_bfloat162(l0, l1); dl[1] = __nv_bfloat162(l2, l3);
}

// ---------------- HMMA GEMM: xi = A @ W^T + b (R8/R10 proven config) -----------
#define GT_SMEM (2 * 32768 + 1024)
__global__ __launch_bounds__(256) void gemm_mma(
    const float* __restrict__ bf_, const float* __restrict__ br_)
{
    extern __shared__ char dsm[];
    __shared__ float sbias[128];
    const unsigned sbase = (smem_u32(dsm) + 1023u) & ~1023u;

    const int tid = threadIdx.x;
    const int wid = tid >> 5, lane = tid & 31;
    const int wm = wid >> 2, wn = wid & 3;
    const int g = lane >> 2, tig = lane & 3;

    const int bx = blockIdx.x;
    const int m_tile = bx / 12;
    const int sub = bx - m_tile * 12;
    const int dir = sub >= 6;
    const int n0 = (dir ? sub - 6 : sub) * 128;
    const int m0 = m_tile * 128;
    float* C = dir ? g_xi_r : g_xi_f;
    const __nv_bfloat16* w2 = g_w2 + (size_t)dir * G3 * 1024;
    const float* bias = dir ? br_ : bf_;

    if (tid < 128) sbias[tid] = bias[n0 + tid];

    const int arow = wm * 64 + (lane & 15);
    const unsigned axm = (unsigned)(arow & 7) * 16u;
    const unsigned acol8 = (unsigned)(lane >> 4) * 16u;
    const int brow = wn * 32 + (lane & 7);
    const unsigned bxm = (unsigned)(lane & 7) * 16u;
    const unsigned bcol8 = (unsigned)((lane >> 3) & 1) * 16u;

    float acc[4][4][4];
#pragma unroll
    for (int mt = 0; mt < 4; mt++)
#pragma unroll
        for (int nt = 0; nt < 4; nt++)
#pragma unroll
            for (int q = 0; q < 4; q++) acc[mt][nt][q] = 0.f;

    const int lrow = tid & 127;
    const int isb = tid >> 7;
    auto load_chunk = [&](int c, int buf) {
        int acol, bcol;
        if (c < 8)       { acol = c * 64;              bcol = c * 64; }
        else if (c < 16) { acol = 512 + (c - 8) * 64;  bcol = (c - 8) * 64; }
        else             { acol = (c - 16) * 64;       bcol = 512 + (c - 16) * 64; }
        const __nv_bfloat16* src = isb
            ? (w2 + (size_t)(n0 + lrow) * 1024 + bcol)
            : (g_a2 + (size_t)(m0 + lrow) * 1024 + acol);
        const unsigned dbuf = sbase + (unsigned)buf * 32768u + (unsigned)isb * 16384u;
        const unsigned rowo = (unsigned)lrow * 128u;
#pragma unroll
        for (int q = 0; q < 8; q++)
            cp_async16(dbuf + SWZ(rowo + q * 16u), src + q * 8);
        CP_COMMIT();
    };

    load_chunk(0, 0);

    for (int c = 0; c < 24; c++) {
        const int buf = c & 1;
        if (c < 23) { load_chunk(c + 1, (c + 1) & 1); CP_WAIT(1); }
        else        { CP_WAIT(0); }
        __syncthreads();

        const unsigned abuf = sbase + (unsigned)buf * 32768u;
        const unsigned bbuf = abuf + 16384u;
#pragma unroll
        for (int ks = 0; ks < 4; ks++) {
            const unsigned akc = (unsigned)(ks * 32) + acol8;
            const unsigned bkc = (unsigned)(ks * 32) + bcol8;
            unsigned af[4][4];
#pragma unroll
            for (int mt = 0; mt < 4; mt++)
                ldsm_x4(af[mt], abuf + (unsigned)(arow + mt * 16) * 128u + (akc ^ axm));
            unsigned bfr[4][2];
#pragma unroll
            for (int nt = 0; nt < 4; nt++)
                ldsm_x2(bfr[nt], bbuf + (unsigned)(brow + nt * 8) * 128u + (bkc ^ bxm));
#pragma unroll
            for (int mt = 0; mt < 4; mt++)
#pragma unroll
                for (int nt = 0; nt < 4; nt++)
                    mma_bf16(acc[mt][nt], af[mt], bfr[nt]);
        }
        __syncthreads();
    }

#pragma unroll
    for (int mt = 0; mt < 4; mt++) {
        const int m = m0 + wm * 64 + mt * 16 + g;
#pragma unroll
        for (int nt = 0; nt < 4; nt++) {
            const int nloc = wn * 32 + nt * 8 + 2 * tig;
            const float b0 = sbias[nloc], b1 = sbias[nloc + 1];
            float2 v0, v1;
            v0.x = acc[mt][nt][0] + b0; v0.y = acc[mt][nt][1] + b1;
            v1.x = acc[mt][nt][2] + b0; v1.y = acc[mt][nt][3] + b1;
            *(float2*)(C + (size_t)m * G3 + n0 + nloc) = v0;
            *(float2*)(C + (size_t)(m + 8) * G3 + n0 + nloc) = v1;
        }
    }
}

// ---------------- cluster-persistent GRU recurrence (tensor-core step) --------
// R10 shell + DOUBLE-BUFFERED h-state: step s reads A-buf (s&1), DSMEM-writes
// buf (s^1)&1 -> ONE cluster barrier pair per step (hidden under xi prefetch).
// Layer 0 writes split-bf16 g_a2 directly (feeds layer-1 GEMM, no convert).
#define RW_HI    0u
#define RW_LO    98304u
#define RA_BASE  196608u      // two buffers of 16KB (hi 8KB + lo 8KB)
#define GRU_SMEM_BYTES 229376u

__global__ void __launch_bounds__(256, 1) __cluster_dims__(4, 1, 1)
gru_cluster(const float* __restrict__ whh_f, const float* __restrict__ whh_r,
            const float* __restrict__ bhh_f, const float* __restrict__ bhh_r,
            int layer)
{
    extern __shared__ char rsm[];
    const unsigned sb = smem_u32(rsm);

    const unsigned rank = ctarank();
    const int cid = blockIdx.x >> 2;
    const int dir = cid >> 4;
    const int bg  = cid & 15;

    const float* xi  = dir ? g_xi_r : g_xi_f;
    const float* whh = dir ? whh_r : whh_f;
    const float* bhh = dir ? bhh_r : bhh_f;
    const int zoff = dir * HID;

    const int tid = threadIdx.x;
    const int w = tid >> 5, lane = tid & 31;

    // ---- stage Whh -> SMEM bf16 hi/lo, rows n = g*64+hl, 512B, row-xor swizzle
    if (tid < 192) {
        const int n = tid;
        const int gg = n >> 6, hl = n & 63;
        const float* wrow = whh + (size_t)(gg * HID + rank * 64 + hl) * HID;
        const unsigned xm = (unsigned)(n & 7) * 16u;
#pragma unroll 4
        for (int kk = 0; kk < 128; kk++) {
            const float2 v = *(const float2*)(wrow + 2 * kk);
            const float h0f = __bfloat162float(__float2bfloat16(v.x));
            const float h1f = __bfloat162float(__float2bfloat16(v.y));
            const unsigned off = ((unsigned)(kk * 4)) ^ xm;
            *(unsigned*)(rsm + (unsigned)n * 512u + RW_HI + off) = pack_bf16(v.x, v.y);
            *(unsigned*)(rsm + (unsigned)n * 512u + RW_LO + off) =
                pack_bf16(v.x - h0f, v.y - h1f);
        }
    }
    // zero both A buffers (h0 = 0)
    for (unsigned i = tid; i < 8192; i += 256)
        *(unsigned*)(rsm + RA_BASE + i * 4) = 0u;
    __syncthreads();
    cluster_sync_full();

    // ---- per-lane geometry ----
    const int hl2 = w * 8 + (lane & 3) * 2;
    const int hg0 = rank * 64 + hl2;
    const int b0 = lane >> 2;
    const float2 br2 = *(const float2*)(bhh + hg0);
    const float2 bz2 = *(const float2*)(bhh + HID + hg0);
    const float2 bn2 = *(const float2*)(bhh + 2 * HID + hg0);

    const unsigned arow_off = (unsigned)(lane & 15) * 512u;
    const unsigned axor = (unsigned)((lane & 15) & 7) * 16u;
    const unsigned acol = (unsigned)(lane >> 4) * 16u;
    const unsigned bxor = (unsigned)(lane & 7) * 16u;
    const unsigned bcol = (unsigned)(lane >> 3) * 16u;
    unsigned wrow_off[3];
#pragma unroll
    for (int gg = 0; gg < 3; gg++)
        wrow_off[gg] = (unsigned)((gg * 64 + w * 8 + (lane & 7)) * 512);

    // h-state offsets relative to a buffer base (hi part; lo = +8192)
    const unsigned xw0 = (unsigned)(b0 & 7) * 16u;
    const unsigned xw1 = (unsigned)((b0 + 8) & 7) * 16u;
    const unsigned relH0 = (unsigned)b0 * 512u + (((unsigned)(2 * hg0)) ^ xw0);
    const unsigned relH1 = (unsigned)(b0 + 8) * 512u + (((unsigned)(2 * hg0)) ^ xw1);
    unsigned rmap[4];
#pragma unroll
    for (unsigned r = 0; r < 4; r++) rmap[r] = mapa_sh(sb, r);

    // initial xi prefetch
    float2 xig[3][2];
    {
        const int t0 = dir ? (SEQL - 1) : 0;
        const float* xp0 = xi + ((size_t)(bg * 16 + b0) * SEQL + t0) * G3 + hg0;
        const float* xp1 = xi + ((size_t)(bg * 16 + b0 + 8) * SEQL + t0) * G3 + hg0;
#pragma unroll
        for (int gg = 0; gg < 3; gg++) {
            xig[gg][0] = *(const float2*)(xp0 + gg * HID);
            xig[gg][1] = *(const float2*)(xp1 + gg * HID);
        }
    }

    for (int s = 0; s < SEQL; s++) {
        const int t = dir ? (SEQL - 1 - s) : s;
        const unsigned rdb = RA_BASE + (unsigned)(s & 1) * 16384u;       // read buf
        const unsigned wrb = RA_BASE + (unsigned)((s + 1) & 1) * 16384u; // write buf

        float acc[3][4];
#pragma unroll
        for (int gg = 0; gg < 3; gg++)
#pragma unroll
            for (int q = 0; q < 4; q++) acc[gg][q] = 0.f;

        // ---- 3-term split-bf16 HMMA: hh, lh, hl ----
#pragma unroll
        for (int term = 0; term < 3; term++) {
            const unsigned Ab = sb + rdb + ((term == 1) ? 8192u : 0u);
            const unsigned Wb = sb + ((term == 2) ? RW_LO : RW_HI);
#pragma unroll
            for (int ks2 = 0; ks2 < 8; ks2++) {
                const unsigned k0b = (unsigned)(ks2 * 64);
                unsigned af0[4], af1[4];
                ldsm_x4(af0, Ab + arow_off + ((k0b + acol) ^ axor));
                ldsm_x4(af1, Ab + arow_off + ((k0b + 32u + acol) ^ axor));
#pragma unroll
                for (int gg = 0; gg < 3; gg++) {
                    unsigned bfr[4];
                    ldsm_x4(bfr, Wb + wrow_off[gg] + ((k0b + bcol) ^ bxor));
                    mma_bf16(acc[gg], af0, bfr);
                    mma_bf16(acc[gg], af1, bfr + 2);
                }
            }
        }

        // ---- h_prev from read buffer ----
        float hp[2][2];
        {
            const __nv_bfloat162 h0w = *(const __nv_bfloat162*)(rsm + rdb + relH0);
            const __nv_bfloat162 l0w = *(const __nv_bfloat162*)(rsm + rdb + 8192u + relH0);
            const __nv_bfloat162 h1w = *(const __nv_bfloat162*)(rsm + rdb + relH1);
            const __nv_bfloat162 l1w = *(const __nv_bfloat162*)(rsm + rdb + 8192u + relH1);
            hp[0][0] = __bfloat162float(h0w.x) + __bfloat162float(l0w.x);
            hp[0][1] = __bfloat162float(h0w.y) + __bfloat162float(l0w.y);
            hp[1][0] = __bfloat162float(h1w.x) + __bfloat162float(l1w.x);
            hp[1][1] = __bfloat162float(h1w.y) + __bfloat162float(l1w.y);
        }

        // ---- epilogue: gates ----
        float hnew[2][2];
#pragma unroll
        for (int bi = 0; bi < 2; bi++) {
#pragma unroll
            for (int hj = 0; hj < 2; hj++) {
                const int q = bi * 2 + hj;
                const float gr = acc[0][q] + (hj ? br2.y : br2.x);
                const float gz = acc[1][q] + (hj ? bz2.y : bz2.x);
                const float gn = acc[2][q] + (hj ? bn2.y : bn2.x);
                const float xr = hj ? xig[0][bi].y : xig[0][bi].x;
                const float xz = hj ? xig[1][bi].y : xig[1][bi].x;
                const float xn = hj ? xig[2][bi].y : xig[2][bi].x;
                const float rg = sigmoid_f(xr + gr);
                const float zg = sigmoid_f(xz + gz);
                const float ng = tanh_f(xn + rg * gn);
                hnew[bi][hj] = (1.f - zg) * ng + zg * hp[bi][hj];
            }
        }

        // pack hi/lo words (shared by DSMEM handoff and layer-0 a2 output)
        unsigned whw[2], wlw[2];
#pragma unroll
        for (int bi = 0; bi < 2; bi++) {
            const float r0 = __bfloat162float(__float2bfloat16(hnew[bi][0]));
            const float r1 = __bfloat162float(__float2bfloat16(hnew[bi][1]));
            whw[bi] = pack_bf16(hnew[bi][0], hnew[bi][1]);
            wlw[bi] = pack_bf16(hnew[bi][0] - r0, hnew[bi][1] - r1);
        }

        // ---- global output ----
#pragma unroll
        for (int bi = 0; bi < 2; bi++) {
            const int b = bg * 16 + b0 + bi * 8;
            const size_t row = (size_t)b * SEQL + t;
            if (layer) {
                *(float2*)(g_seq1 + row * 512 + zoff + hg0) =
                    make_float2(hnew[bi][0], hnew[bi][1]);
            } else {
                *(unsigned*)&g_a2[row * 1024 + zoff + hg0] = whw[bi];
                *(unsigned*)&g_a2[row * 1024 + 512 + zoff + hg0] = wlw[bi];
            }
        }

        // ---- DSMEM handoff into write buffer of all 4 ranks ----
#pragma unroll
        for (unsigned r = 0; r < 4; r++) {
            st_cluster_u32(rmap[r] + wrb + relH0, whw[0]);
            st_cluster_u32(rmap[r] + wrb + 8192u + relH0, wlw[0]);
            st_cluster_u32(rmap[r] + wrb + relH1, whw[1]);
            st_cluster_u32(rmap[r] + wrb + 8192u + relH1, wlw[1]);
        }

        cluster_arrive();   // single barrier pair per step

        if (s + 1 < SEQL) {
            const int tn_ = dir ? (SEQL - 2 - s) : (s + 1);
            const float* xp0 = xi + ((size_t)(bg * 16 + b0) * SEQL + tn_) * G3 + hg0;
            const float* xp1 = xi + ((size_t)(bg * 16 + b0 + 8) * SEQL + tn_) * G3 + hg0;
#pragma unroll
            for (int gg = 0; gg < 3; gg++) {
                xig[gg][0] = *(const float2*)(xp0 + gg * HID);
                xig[gg][1] = *(const float2*)(xp1 + gg * HID);
            }
        }

        cluster_wait();     // h_s visible everywhere; wait hidden by prefetch
    }
}

// ---------------- heads: warp-per-row ------------------------------------------
__global__ __launch_bounds__(256) void fc_heads(
    const float* __restrict__ fc1w, const float* __restrict__ fc1b,
    const float* __restrict__ fc2w, const float* __restrict__ fc2b,
    float* __restrict__ y, float* __restrict__ y2)
{
    __shared__ float ws[11 * 512];
    __shared__ float bsh[11];
    const int tid = threadIdx.x;
    for (int i = tid; i < 5120; i += 256) ws[i] = fc2w[i];
    for (int i = tid; i < 512; i += 256) ws[5120 + i] = fc1w[i];
    if (tid < 10) bsh[tid] = fc2b[tid];
    if (tid == 10) bsh[10] = fc1b[0];
    __syncthreads();

    const int wid = tid >> 5, lane = tid & 31;
    const int bt = blockIdx.x * 8 + wid;
    const float4* row = (const float4*)(g_seq1 + (size_t)bt * 512);
    float4 v[4];
#pragma unroll
    for (int q = 0; q < 4; q++) v[q] = row[q * 32 + lane];

#pragma unroll
    for (int j = 0; j < 11; j++) {
        const float4* wj = (const float4*)(ws + j * 512);
        float s = 0.f;
#pragma unroll
        for (int q = 0; q < 4; q++) {
            const float4 wv = wj[q * 32 + lane];
            s += v[q].x * wv.x + v[q].y * wv.y + v[q].z * wv.z + v[q].w * wv.w;
        }
#pragma unroll
        for (int off = 16; off; off >>= 1) s += __shfl_xor_sync(0xffffffffu, s, off);
        if (lane == 0) {
            if (j < 10) y2[(size_t)bt * 10 + j] = s + bsh[j];
            else        y[bt] = s + bsh[10];
        }
    }
}

__global__ __launch_bounds__(256) void softmax_y_kernel(const float* __restrict__ y) {
    const int b = blockIdx.x;
    __shared__ float sh[256];
    const int tid = threadIdx.x;
    float v = (tid < SEQL) ? y[b * SEQL + tid] : -INFINITY;
    sh[tid] = v; __syncthreads();
    for (int s = 128; s; s >>= 1) {
        if (tid < s) sh[tid] = fmaxf(sh[tid], sh[tid + s]);
        __syncthreads();
    }
    const float mx = sh[0]; __syncthreads();
    const float e = (tid < SEQL) ? __expf(v - mx) : 0.f;
    sh[tid] = e; __syncthreads();
    for (int s = 128; s; s >>= 1) {
        if (tid < s) sh[tid] += sh[tid + s];
        __syncthreads();
    }
    const float inv = 1.f / sh[0];
    if (tid < SEQL) g_p[b * SEQL + tid] = e * inv * 0.1f;
}

__global__ __launch_bounds__(256) void softmax_y2_kernel(
    const float* __restrict__ y2, float* __restrict__ y3)
{
    const int b = blockIdx.x;
    const int tid = threadIdx.x;
    __shared__ float sh[256];
    const float* src = y2 + (size_t)b * 2000;
    float mx = -INFINITY;
    for (int i = tid; i < 2000; i += 256) mx = fmaxf(mx, src[i]);
    sh[tid] = mx; __syncthreads();
    for (int s = 128; s; s >>= 1) {
        if (tid < s) sh[tid] = fmaxf(sh[tid], sh[tid + s]);
        __syncthreads();
    }
    mx = sh[0]; __syncthreads();
    float sum = 0.f;
    for (int i = tid; i < 2000; i += 256) sum += __expf(src[i] - mx);
    sh[tid] = sum; __syncthreads();
    for (int s = 128; s; s >>= 1) {
        if (tid < s) sh[tid] += sh[tid + s];
        __syncthreads();
    }
    const float inv = 1.f / sh[0];
    for (int i = tid; i < 2000; i += 256)
        y3[(size_t)b * 2000 + i] = __expf(src[i] - mx) * inv + g_p[b * SEQL + i / 10];
}

// ---------------- driver ------------------------------------------------------
extern "C" void kernel_launch(void* const* d_in, const int* in_sizes, int n_in,
                              void* d_out, int out_size) {
    (void)in_sizes; (void)n_in; (void)out_size;
    const float* x        = (const float*)d_in[0];
    const float* w_ih_l0  = (const float*)d_in[1];
    const float* w_hh_l0  = (const float*)d_in[2];
    const float* b_ih_l0  = (const float*)d_in[3];
    const float* b_hh_l0  = (const float*)d_in[4];
    const float* w_ih_l0r = (const float*)d_in[5];
    const float* w_hh_l0r = (const float*)d_in[6];
    const float* b_ih_l0r = (const float*)d_in[7];
    const float* b_hh_l0r = (const float*)d_in[8];
    const float* w_ih_l1  = (const float*)d_in[9];
    const float* w_hh_l1  = (const float*)d_in[10];
    const float* b_ih_l1  = (const float*)d_in[11];
    const float* b_hh_l1  = (const float*)d_in[12];
    const float* w_ih_l1r = (const float*)d_in[13];
    const float* w_hh_l1r = (const float*)d_in[14];
    const float* b_ih_l1r = (const float*)d_in[15];
    const float* b_hh_l1r = (const float*)d_in[16];
    const float* fc1_w    = (const float*)d_in[17];
    const float* fc1_b    = (const float*)d_in[18];
    const float* fc2_w    = (const float*)d_in[19];
    const float* fc2_b    = (const float*)d_in[20];

    float* y  = (float*)d_out;
    float* y2 = y + BL;
    float* y3 = y2 + BL * 10;

    static int configured = 0;
    if (!configured) {
        cudaFuncSetAttribute(gru_cluster, cudaFuncAttributeMaxDynamicSharedMemorySize,
                             GRU_SMEM_BYTES);
        cudaFuncSetAttribute(gemm_mma, cudaFuncAttributeMaxDynamicSharedMemorySize,
                             GT_SMEM);
        configured = 1;
    }

    __nv_bfloat16* a2p = nullptr;
    __nv_bfloat16* w2p = nullptr;
    cudaGetSymbolAddress((void**)&a2p, g_a2);
    cudaGetSymbolAddress((void**)&w2p, g_w2);

    const int A_ELEM = BL * 512;
    const int W_ELEM = G3 * 512;

    // ---- layer 0 ----
    convert_split<<<A_ELEM / 1024, 256>>>(x, a2p, A_ELEM);
    convert_split<<<W_ELEM / 1024, 256>>>(w_ih_l0,  w2p,                     W_ELEM);
    convert_split<<<W_ELEM / 1024, 256>>>(w_ih_l0r, w2p + (size_t)G3 * 1024, W_ELEM);
    gemm_mma<<<(BL / 128) * 12, 256, GT_SMEM>>>(b_ih_l0, b_ih_l0r);
    gru_cluster<<<128, 256, GRU_SMEM_BYTES>>>(w_hh_l0, w_hh_l0r, b_hh_l0, b_hh_l0r, 0);
    // layer-0 recurrence wrote split-bf16 g_a2 directly (no convert needed)

    // ---- layer 1 ----
    convert_split<<<W_ELEM / 1024, 256>>>(w_ih_l1,  w2p,                     W_ELEM);
    convert_split<<<W_ELEM / 1024, 256>>>(w_ih_l1r, w2p + (size_t)G3 * 1024, W_ELEM);
    gemm_mma<<<(BL / 128) * 12, 256, GT_SMEM>>>(b_ih_l1, b_ih_l1r);
    gru_cluster<<<128, 256, GRU_SMEM_BYTES>>>(w_hh_l1, w_hh_l1r, b_hh_l1, b_hh_l1r, 1);

    // ---- heads ----
    fc_heads<<<BL / 8, 256>>>(fc1_w, fc1_b, fc2_w, fc2_b, y, y2);
    softmax_y_kernel<<<BATCH, 256>>>(y);
    softmax_y2_kernel<<<BATCH, 256>>>(y2, y3);
}

// round 12
// speedup vs baseline: 2.9908x; 1.2574x over previous
#include <cuda_runtime.h>
#include <cuda_bf16.h>
#include <cuda_fp16.h>
#include <math.h>

// Problem constants
#define BATCH 256
#define SEQL  200
#define INF   512
#define HID   256
#define G3    768
#define BL    (BATCH*SEQL)   // 51200

// ---------------- scratch (device globals) -----------------------------------
__device__ float g_xi_f[(size_t)BL * G3];
__device__ float g_xi_r[(size_t)BL * G3];
__device__ float g_seq1[(size_t)BL * 512];
__device__ float g_p[BL];
__device__ __half g_a2[(size_t)BL * 1024];       // A split fp16: [row][hi(512)|lo(512)]
__device__ __half g_w2[2ull * G3 * 1024];        // W split fp16 per dir

// ---------------- helpers -----------------------------------------------------
__device__ __forceinline__ unsigned smem_u32(const void* p) {
    unsigned r;
    asm("{ .reg .u64 t; cvta.to.shared.u64 t, %1; cvt.u32.u64 %0, t; }"
        : "=r"(r) : "l"(p));
    return r;
}
__device__ __forceinline__ unsigned mapa_sh(unsigned addr, unsigned rank) {
    unsigned r;
    asm("mapa.shared::cluster.u32 %0, %1, %2;" : "=r"(r) : "r"(addr), "r"(rank));
    return r;
}
__device__ __forceinline__ void st_cluster_u32(unsigned addr, unsigned v) {
    asm volatile("st.shared::cluster.u32 [%0], %1;" :: "r"(addr), "r"(v) : "memory");
}
__device__ __forceinline__ void cluster_arrive() {
    asm volatile("barrier.cluster.arrive.aligned;" ::: "memory");
}
__device__ __forceinline__ void cluster_wait() {
    asm volatile("barrier.cluster.wait.aligned;" ::: "memory");
}
__device__ __forceinline__ void cluster_sync_full() {
    cluster_arrive(); cluster_wait();
}
__device__ __forceinline__ unsigned ctarank() {
    unsigned r;
    asm("mov.u32 %0, %%cluster_ctarank;" : "=r"(r));
    return r;
}
__device__ __forceinline__ float sigmoid_f(float x) {
    return __fdividef(1.f, 1.f + __expf(-x));
}
__device__ __forceinline__ float tanh_f(float x) {
    return 1.f - __fdividef(2.f, __expf(2.f * x) + 1.f);
}
__device__ __forceinline__ void cp_async16(unsigned sdst, const void* gsrc) {
    asm volatile("cp.async.cg.shared.global [%0], [%1], 16;"
                 :: "r"(sdst), "l"(gsrc) : "memory");
}
#define CP_COMMIT()  asm volatile("cp.async.commit_group;" ::: "memory")
#define CP_WAIT(n)   asm volatile("cp.async.wait_group %0;" :: "n"(n) : "memory")
#define SWZ(o) ((o) ^ (((o) >> 3) & 0x70))

__device__ __forceinline__ void ldsm_x4(unsigned* r, unsigned addr) {
    asm volatile("ldmatrix.sync.aligned.m8n8.x4.shared.b16 {%0,%1,%2,%3}, [%4];"
                 : "=r"(r[0]), "=r"(r[1]), "=r"(r[2]), "=r"(r[3]) : "r"(addr));
}
__device__ __forceinline__ void ldsm_x2(unsigned* r, unsigned addr) {
    asm volatile("ldmatrix.sync.aligned.m8n8.x2.shared.b16 {%0,%1}, [%2];"
                 : "=r"(r[0]), "=r"(r[1]) : "r"(addr));
}
// fp16 MMA (GEMM path)
__device__ __forceinline__ void mma_f16(float* c, const unsigned* a, const unsigned* b) {
    asm volatile("mma.sync.aligned.m16n8k16.row.col.f32.f16.f16.f32 "
                 "{%0,%1,%2,%3}, {%4,%5,%6,%7}, {%8,%9}, {%0,%1,%2,%3};"
                 : "+f"(c[0]), "+f"(c[1]), "+f"(c[2]), "+f"(c[3])
                 : "r"(a[0]), "r"(a[1]), "r"(a[2]), "r"(a[3]),
                   "r"(b[0]), "r"(b[1]));
}
// bf16 MMA (recurrence path)
__device__ __forceinline__ void mma_bf16(float* c, const unsigned* a, const unsigned* b) {
    asm volatile("mma.sync.aligned.m16n8k16.row.col.f32.bf16.bf16.f32 "
                 "{%0,%1,%2,%3}, {%4,%5,%6,%7}, {%8,%9}, {%0,%1,%2,%3};"
                 : "+f"(c[0]), "+f"(c[1]), "+f"(c[2]), "+f"(c[3])
                 : "r"(a[0]), "r"(a[1]), "r"(a[2]), "r"(a[3]),
                   "r"(b[0]), "r"(b[1]));
}
__device__ __forceinline__ unsigned pack_bf16(float a, float b) {
    __nv_bfloat162 t = __floats2bfloat162_rn(a, b);
    return *(unsigned*)&t;
}
__device__ __forceinline__ unsigned pack_f16(float a, float b) {
    __half2 t = __floats2half2_rn(a, b);
    return *(unsigned*)&t;
}

// ---------------- split-fp16 conversion: src[rows,512] -> dst[rows, hi|lo] ----
__global__ __launch_bounds__(256) void convert_split(
    const float* __restrict__ src, __half* __restrict__ dst, int nelem)
{
    const int idx = (blockIdx.x * 256 + threadIdx.x) * 4;
    if (idx >= nelem) return;
    const int row = idx >> 9, col = idx & 511;
    const float4 v = *(const float4*)(src + idx);
    const __half h0 = __float2half_rn(v.x), h1 = __float2half_rn(v.y);
    const __half h2 = __float2half_rn(v.z), h3 = __float2half_rn(v.w);
    const __half l0 = __float2half_rn(v.x - __half2float(h0));
    const __half l1 = __float2half_rn(v.y - __half2float(h1));
    const __half l2 = __float2half_rn(v.z - __half2float(h2));
    const __half l3 = __float2half_rn(v.w - __half2float(h3));
    __half2* dh = (__half2*)(dst + (size_t)row * 1024 + col);
    __half2* dl = (__half2*)(dst + (size_t)row * 1024 + 512 + col);
    dh[0] = __half2(h0, h1); dh[1] = __half2(h2, h3);
    dl[0] = __half2(l0, l1); dl[1] = __half2(l2, l3);
}

// ---------------- HMMA GEMM: xi = A @ W^T + b (fp16 2-term split) --------------
// K_eff = 1024 (ah*bh + al*bh), 16 chunks of 64. Skeleton identical to the
// proven R8/R10 config; only dtype and chunk count changed.
#define GT_SMEM (2 * 32768 + 1024)
__global__ __launch_bounds__(256) void gemm_mma(
    const float* __restrict__ bf_, const float* __restrict__ br_)
{
    extern __shared__ char dsm[];
    __shared__ float sbias[128];
    const unsigned sbase = (smem_u32(dsm) + 1023u) & ~1023u;

    const int tid = threadIdx.x;
    const int wid = tid >> 5, lane = tid & 31;
    const int wm = wid >> 2, wn = wid & 3;
    const int g = lane >> 2, tig = lane & 3;

    const int bx = blockIdx.x;
    const int m_tile = bx / 12;
    const int sub = bx - m_tile * 12;
    const int dir = sub >= 6;
    const int n0 = (dir ? sub - 6 : sub) * 128;
    const int m0 = m_tile * 128;
    float* C = dir ? g_xi_r : g_xi_f;
    const __half* w2 = g_w2 + (size_t)dir * G3 * 1024;
    const float* bias = dir ? br_ : bf_;

    if (tid < 128) sbias[tid] = bias[n0 + tid];

    const int arow = wm * 64 + (lane & 15);
    const unsigned axm = (unsigned)(arow & 7) * 16u;
    const unsigned acol8 = (unsigned)(lane >> 4) * 16u;
    const int brow = wn * 32 + (lane & 7);
    const unsigned bxm = (unsigned)(lane & 7) * 16u;
    const unsigned bcol8 = (unsigned)((lane >> 3) & 1) * 16u;

    float acc[4][4][4];
#pragma unroll
    for (int mt = 0; mt < 4; mt++)
#pragma unroll
        for (int nt = 0; nt < 4; nt++)
#pragma unroll
            for (int q = 0; q < 4; q++) acc[mt][nt][q] = 0.f;

    const int lrow = tid & 127;
    const int isb = tid >> 7;
    auto load_chunk = [&](int c, int buf) {
        int acol, bcol;
        if (c < 8) { acol = c * 64;             bcol = c * 64; }        // ah*bh
        else       { acol = 512 + (c - 8) * 64; bcol = (c - 8) * 64; }  // al*bh
        const __half* src = isb
            ? (w2 + (size_t)(n0 + lrow) * 1024 + bcol)
            : (g_a2 + (size_t)(m0 + lrow) * 1024 + acol);
        const unsigned dbuf = sbase + (unsigned)buf * 32768u + (unsigned)isb * 16384u;
        const unsigned rowo = (unsigned)lrow * 128u;
#pragma unroll
        for (int q = 0; q < 8; q++)
            cp_async16(dbuf + SWZ(rowo + q * 16u), src + q * 8);
        CP_COMMIT();
    };

    load_chunk(0, 0);

    for (int c = 0; c < 16; c++) {
        const int buf = c & 1;
        if (c < 15) { load_chunk(c + 1, (c + 1) & 1); CP_WAIT(1); }
        else        { CP_WAIT(0); }
        __syncthreads();

        const unsigned abuf = sbase + (unsigned)buf * 32768u;
        const unsigned bbuf = abuf + 16384u;
#pragma unroll
        for (int ks = 0; ks < 4; ks++) {
            const unsigned akc = (unsigned)(ks * 32) + acol8;
            const unsigned bkc = (unsigned)(ks * 32) + bcol8;
            unsigned af[4][4];
#pragma unroll
            for (int mt = 0; mt < 4; mt++)
                ldsm_x4(af[mt], abuf + (unsigned)(arow + mt * 16) * 128u + (akc ^ axm));
            unsigned bfr[4][2];
#pragma unroll
            for (int nt = 0; nt < 4; nt++)
                ldsm_x2(bfr[nt], bbuf + (unsigned)(brow + nt * 8) * 128u + (bkc ^ bxm));
#pragma unroll
            for (int mt = 0; mt < 4; mt++)
#pragma unroll
                for (int nt = 0; nt < 4; nt++)
                    mma_f16(acc[mt][nt], af[mt], bfr[nt]);
        }
        __syncthreads();
    }

#pragma unroll
    for (int mt = 0; mt < 4; mt++) {
        const int m = m0 + wm * 64 + mt * 16 + g;
#pragma unroll
        for (int nt = 0; nt < 4; nt++) {
            const int nloc = wn * 32 + nt * 8 + 2 * tig;
            const float b0 = sbias[nloc], b1 = sbias[nloc + 1];
            float2 v0, v1;
            v0.x = acc[mt][nt][0] + b0; v0.y = acc[mt][nt][1] + b1;
            v1.x = acc[mt][nt][2] + b0; v1.y = acc[mt][nt][3] + b1;
            *(float2*)(C + (size_t)m * G3 + n0 + nloc) = v0;
            *(float2*)(C + (size_t)(m + 8) * G3 + n0 + nloc) = v1;
        }
    }
}

// ---------------- cluster-persistent GRU recurrence (tensor-core step) --------
// Unchanged R11 scheme (bf16 3-term, double-buffered h-state, one barrier/step).
// Layer-0 output now packs fp16 hi/lo into g_a2 for the layer-1 GEMM.
#define RW_HI    0u
#define RW_LO    98304u
#define RA_BASE  196608u      // two buffers of 16KB (hi 8KB + lo 8KB)
#define GRU_SMEM_BYTES 229376u

__global__ void __launch_bounds__(256, 1) __cluster_dims__(4, 1, 1)
gru_cluster(const float* __restrict__ whh_f, const float* __restrict__ whh_r,
            const float* __restrict__ bhh_f, const float* __restrict__ bhh_r,
            int layer)
{
    extern __shared__ char rsm[];
    const unsigned sb = smem_u32(rsm);

    const unsigned rank = ctarank();
    const int cid = blockIdx.x >> 2;
    const int dir = cid >> 4;
    const int bg  = cid & 15;

    const float* xi  = dir ? g_xi_r : g_xi_f;
    const float* whh = dir ? whh_r : whh_f;
    const float* bhh = dir ? bhh_r : bhh_f;
    const int zoff = dir * HID;

    const int tid = threadIdx.x;
    const int w = tid >> 5, lane = tid & 31;

    // ---- stage Whh -> SMEM bf16 hi/lo, rows n = g*64+hl, 512B, row-xor swizzle
    if (tid < 192) {
        const int n = tid;
        const int gg = n >> 6, hl = n & 63;
        const float* wrow = whh + (size_t)(gg * HID + rank * 64 + hl) * HID;
        const unsigned xm = (unsigned)(n & 7) * 16u;
#pragma unroll 4
        for (int kk = 0; kk < 128; kk++) {
            const float2 v = *(const float2*)(wrow + 2 * kk);
            const float h0f = __bfloat162float(__float2bfloat16(v.x));
            const float h1f = __bfloat162float(__float2bfloat16(v.y));
            const unsigned off = ((unsigned)(kk * 4)) ^ xm;
            *(unsigned*)(rsm + (unsigned)n * 512u + RW_HI + off) = pack_bf16(v.x, v.y);
            *(unsigned*)(rsm + (unsigned)n * 512u + RW_LO + off) =
                pack_bf16(v.x - h0f, v.y - h1f);
        }
    }
    // zero both A buffers (h0 = 0)
    for (unsigned i = tid; i < 8192; i += 256)
        *(unsigned*)(rsm + RA_BASE + i * 4) = 0u;
    __syncthreads();
    cluster_sync_full();

    // ---- per-lane geometry ----
    const int hl2 = w * 8 + (lane & 3) * 2;
    const int hg0 = rank * 64 + hl2;
    const int b0 = lane >> 2;
    const float2 br2 = *(const float2*)(bhh + hg0);
    const float2 bz2 = *(const float2*)(bhh + HID + hg0);
    const float2 bn2 = *(const float2*)(bhh + 2 * HID + hg0);

    const unsigned arow_off = (unsigned)(lane & 15) * 512u;
    const unsigned axor = (unsigned)((lane & 15) & 7) * 16u;
    const unsigned acol = (unsigned)(lane >> 4) * 16u;
    const unsigned bxor = (unsigned)(lane & 7) * 16u;
    const unsigned bcol = (unsigned)(lane >> 3) * 16u;
    unsigned wrow_off[3];
#pragma unroll
    for (int gg = 0; gg < 3; gg++)
        wrow_off[gg] = (unsigned)((gg * 64 + w * 8 + (lane & 7)) * 512);

    const unsigned xw0 = (unsigned)(b0 & 7) * 16u;
    const unsigned xw1 = (unsigned)((b0 + 8) & 7) * 16u;
    const unsigned relH0 = (unsigned)b0 * 512u + (((unsigned)(2 * hg0)) ^ xw0);
    const unsigned relH1 = (unsigned)(b0 + 8) * 512u + (((unsigned)(2 * hg0)) ^ xw1);
    unsigned rmap[4];
#pragma unroll
    for (unsigned r = 0; r < 4; r++) rmap[r] = mapa_sh(sb, r);

    // initial xi prefetch
    float2 xig[3][2];
    {
        const int t0 = dir ? (SEQL - 1) : 0;
        const float* xp0 = xi + ((size_t)(bg * 16 + b0) * SEQL + t0) * G3 + hg0;
        const float* xp1 = xi + ((size_t)(bg * 16 + b0 + 8) * SEQL + t0) * G3 + hg0;
#pragma unroll
        for (int gg = 0; gg < 3; gg++) {
            xig[gg][0] = *(const float2*)(xp0 + gg * HID);
            xig[gg][1] = *(const float2*)(xp1 + gg * HID);
        }
    }

    for (int s = 0; s < SEQL; s++) {
        const int t = dir ? (SEQL - 1 - s) : s;
        const unsigned rdb = RA_BASE + (unsigned)(s & 1) * 16384u;
        const unsigned wrb = RA_BASE + (unsigned)((s + 1) & 1) * 16384u;

        float acc[3][4];
#pragma unroll
        for (int gg = 0; gg < 3; gg++)
#pragma unroll
            for (int q = 0; q < 4; q++) acc[gg][q] = 0.f;

        // ---- 3-term split-bf16 HMMA: hh, lh, hl ----
#pragma unroll
        for (int term = 0; term < 3; term++) {
            const unsigned Ab = sb + rdb + ((term == 1) ? 8192u : 0u);
            const unsigned Wb = sb + ((term == 2) ? RW_LO : RW_HI);
#pragma unroll
            for (int ks2 = 0; ks2 < 8; ks2++) {
                const unsigned k0b = (unsigned)(ks2 * 64);
                unsigned af0[4], af1[4];
                ldsm_x4(af0, Ab + arow_off + ((k0b + acol) ^ axor));
                ldsm_x4(af1, Ab + arow_off + ((k0b + 32u + acol) ^ axor));
#pragma unroll
                for (int gg = 0; gg < 3; gg++) {
                    unsigned bfr[4];
                    ldsm_x4(bfr, Wb + wrow_off[gg] + ((k0b + bcol) ^ bxor));
                    mma_bf16(acc[gg], af0, bfr);
                    mma_bf16(acc[gg], af1, bfr + 2);
                }
            }
        }

        // ---- h_prev from read buffer ----
        float hp[2][2];
        {
            const __nv_bfloat162 h0w = *(const __nv_bfloat162*)(rsm + rdb + relH0);
            const __nv_bfloat162 l0w = *(const __nv_bfloat162*)(rsm + rdb + 8192u + relH0);
            const __nv_bfloat162 h1w = *(const __nv_bfloat162*)(rsm + rdb + relH1);
            const __nv_bfloat162 l1w = *(const __nv_bfloat162*)(rsm + rdb + 8192u + relH1);
            hp[0][0] = __bfloat162float(h0w.x) + __bfloat162float(l0w.x);
            hp[0][1] = __bfloat162float(h0w.y) + __bfloat162float(l0w.y);
            hp[1][0] = __bfloat162float(h1w.x) + __bfloat162float(l1w.x);
            hp[1][1] = __bfloat162float(h1w.y) + __bfloat162float(l1w.y);
        }

        // ---- epilogue: gates ----
        float hnew[2][2];
#pragma unroll
        for (int bi = 0; bi < 2; bi++) {
#pragma unroll
            for (int hj = 0; hj < 2; hj++) {
                const int q = bi * 2 + hj;
                const float gr = acc[0][q] + (hj ? br2.y : br2.x);
                const float gz = acc[1][q] + (hj ? bz2.y : bz2.x);
                const float gn = acc[2][q] + (hj ? bn2.y : bn2.x);
                const float xr = hj ? xig[0][bi].y : xig[0][bi].x;
                const float xz = hj ? xig[1][bi].y : xig[1][bi].x;
                const float xn = hj ? xig[2][bi].y : xig[2][bi].x;
                const float rg = sigmoid_f(xr + gr);
                const float zg = sigmoid_f(xz + gz);
                const float ng = tanh_f(xn + rg * gn);
                hnew[bi][hj] = (1.f - zg) * ng + zg * hp[bi][hj];
            }
        }

        // pack bf16 hi/lo words for DSMEM handoff
        unsigned whw[2], wlw[2];
#pragma unroll
        for (int bi = 0; bi < 2; bi++) {
            const float r0 = __bfloat162float(__float2bfloat16(hnew[bi][0]));
            const float r1 = __bfloat162float(__float2bfloat16(hnew[bi][1]));
            whw[bi] = pack_bf16(hnew[bi][0], hnew[bi][1]);
            wlw[bi] = pack_bf16(hnew[bi][0] - r0, hnew[bi][1] - r1);
        }

        // ---- global output ----
#pragma unroll
        for (int bi = 0; bi < 2; bi++) {
            const int b = bg * 16 + b0 + bi * 8;
            const size_t row = (size_t)b * SEQL + t;
            if (layer) {
                *(float2*)(g_seq1 + row * 512 + zoff + hg0) =
                    make_float2(hnew[bi][0], hnew[bi][1]);
            } else {
                // fp16 hi/lo for the layer-1 GEMM
                const float f0 = __half2float(__float2half_rn(hnew[bi][0]));
                const float f1 = __half2float(__float2half_rn(hnew[bi][1]));
                *(unsigned*)&g_a2[row * 1024 + zoff + hg0] =
                    pack_f16(hnew[bi][0], hnew[bi][1]);
                *(unsigned*)&g_a2[row * 1024 + 512 + zoff + hg0] =
                    pack_f16(hnew[bi][0] - f0, hnew[bi][1] - f1);
            }
        }

        // ---- DSMEM handoff into write buffer of all 4 ranks ----
#pragma unroll
        for (unsigned r = 0; r < 4; r++) {
            st_cluster_u32(rmap[r] + wrb + relH0, whw[0]);
            st_cluster_u32(rmap[r] + wrb + 8192u + relH0, wlw[0]);
            st_cluster_u32(rmap[r] + wrb + relH1, whw[1]);
            st_cluster_u32(rmap[r] + wrb + 8192u + relH1, wlw[1]);
        }

        cluster_arrive();

        if (s + 1 < SEQL) {
            const int tn_ = dir ? (SEQL - 2 - s) : (s + 1);
            const float* xp0 = xi + ((size_t)(bg * 16 + b0) * SEQL + tn_) * G3 + hg0;
            const float* xp1 = xi + ((size_t)(bg * 16 + b0 + 8) * SEQL + tn_) * G3 + hg0;
#pragma unroll
            for (int gg = 0; gg < 3; gg++) {
                xig[gg][0] = *(const float2*)(xp0 + gg * HID);
                xig[gg][1] = *(const float2*)(xp1 + gg * HID);
            }
        }

        cluster_wait();
    }
}

// ---------------- heads: warp-per-row ------------------------------------------
__global__ __launch_bounds__(256) void fc_heads(
    const float* __restrict__ fc1w, const float* __restrict__ fc1b,
    const float* __restrict__ fc2w, const float* __restrict__ fc2b,
    float* __restrict__ y, float* __restrict__ y2)
{
    __shared__ float ws[11 * 512];
    __shared__ float bsh[11];
    const int tid = threadIdx.x;
    for (int i = tid; i < 5120; i += 256) ws[i] = fc2w[i];
    for (int i = tid; i < 512; i += 256) ws[5120 + i] = fc1w[i];
    if (tid < 10) bsh[tid] = fc2b[tid];
    if (tid == 10) bsh[10] = fc1b[0];
    __syncthreads();

    const int wid = tid >> 5, lane = tid & 31;
    const int bt = blockIdx.x * 8 + wid;
    const float4* row = (const float4*)(g_seq1 + (size_t)bt * 512);
    float4 v[4];
#pragma unroll
    for (int q = 0; q < 4; q++) v[q] = row[q * 32 + lane];

#pragma unroll
    for (int j = 0; j < 11; j++) {
        const float4* wj = (const float4*)(ws + j * 512);
        float s = 0.f;
#pragma unroll
        for (int q = 0; q < 4; q++) {
            const float4 wv = wj[q * 32 + lane];
            s += v[q].x * wv.x + v[q].y * wv.y + v[q].z * wv.z + v[q].w * wv.w;
        }
#pragma unroll
        for (int off = 16; off; off >>= 1) s += __shfl_xor_sync(0xffffffffu, s, off);
        if (lane == 0) {
            if (j < 10) y2[(size_t)bt * 10 + j] = s + bsh[j];
            else        y[bt] = s + bsh[10];
        }
    }
}

__global__ __launch_bounds__(256) void softmax_y_kernel(const float* __restrict__ y) {
    const int b = blockIdx.x;
    __shared__ float sh[256];
    const int tid = threadIdx.x;
    float v = (tid < SEQL) ? y[b * SEQL + tid] : -INFINITY;
    sh[tid] = v; __syncthreads();
    for (int s = 128; s; s >>= 1) {
        if (tid < s) sh[tid] = fmaxf(sh[tid], sh[tid + s]);
        __syncthreads();
    }
    const float mx = sh[0]; __syncthreads();
    const float e = (tid < SEQL) ? __expf(v - mx) : 0.f;
    sh[tid] = e; __syncthreads();
    for (int s = 128; s; s >>= 1) {
        if (tid < s) sh[tid] += sh[tid + s];
        __syncthreads();
    }
    const float inv = 1.f / sh[0];
    if (tid < SEQL) g_p[b * SEQL + tid] = e * inv * 0.1f;
}

__global__ __launch_bounds__(256) void softmax_y2_kernel(
    const float* __restrict__ y2, float* __restrict__ y3)
{
    const int b = blockIdx.x;
    const int tid = threadIdx.x;
    __shared__ float sh[256];
    const float* src = y2 + (size_t)b * 2000;
    float mx = -INFINITY;
    for (int i = tid; i < 2000; i += 256) mx = fmaxf(mx, src[i]);
    sh[tid] = mx; __syncthreads();
    for (int s = 128; s; s >>= 1) {
        if (tid < s) sh[tid] = fmaxf(sh[tid], sh[tid + s]);
        __syncthreads();
    }
    mx = sh[0]; __syncthreads();
    float sum = 0.f;
    for (int i = tid; i < 2000; i += 256) sum += __expf(src[i] - mx);
    sh[tid] = sum; __syncthreads();
    for (int s = 128; s; s >>= 1) {
        if (tid < s) sh[tid] += sh[tid + s];
        __syncthreads();
    }
    const float inv = 1.f / sh[0];
    for (int i = tid; i < 2000; i += 256)
        y3[(size_t)b * 2000 + i] = __expf(src[i] - mx) * inv + g_p[b * SEQL + i / 10];
}

// ---------------- driver ------------------------------------------------------
extern "C" void kernel_launch(void* const* d_in, const int* in_sizes, int n_in,
                              void* d_out, int out_size) {
    (void)in_sizes; (void)n_in; (void)out_size;
    const float* x        = (const float*)d_in[0];
    const float* w_ih_l0  = (const float*)d_in[1];
    const float* w_hh_l0  = (const float*)d_in[2];
    const float* b_ih_l0  = (const float*)d_in[3];
    const float* b_hh_l0  = (const float*)d_in[4];
    const float* w_ih_l0r = (const float*)d_in[5];
    const float* w_hh_l0r = (const float*)d_in[6];
    const float* b_ih_l0r = (const float*)d_in[7];
    const float* b_hh_l0r = (const float*)d_in[8];
    const float* w_ih_l1  = (const float*)d_in[9];
    const float* w_hh_l1  = (const float*)d_in[10];
    const float* b_ih_l1  = (const float*)d_in[11];
    const float* b_hh_l1  = (const float*)d_in[12];
    const float* w_ih_l1r = (const float*)d_in[13];
    const float* w_hh_l1r = (const float*)d_in[14];
    const float* b_ih_l1r = (const float*)d_in[15];
    const float* b_hh_l1r = (const float*)d_in[16];
    const float* fc1_w    = (const float*)d_in[17];
    const float* fc1_b    = (const float*)d_in[18];
    const float* fc2_w    = (const float*)d_in[19];
    const float* fc2_b    = (const float*)d_in[20];

    float* y  = (float*)d_out;
    float* y2 = y + BL;
    float* y3 = y2 + BL * 10;

    static int configured = 0;
    if (!configured) {
        cudaFuncSetAttribute(gru_cluster, cudaFuncAttributeMaxDynamicSharedMemorySize,
                             GRU_SMEM_BYTES);
        cudaFuncSetAttribute(gemm_mma, cudaFuncAttributeMaxDynamicSharedMemorySize,
                             GT_SMEM);
        configured = 1;
    }

    __half* a2p = nullptr;
    __half* w2p = nullptr;
    cudaGetSymbolAddress((void**)&a2p, g_a2);
    cudaGetSymbolAddress((void**)&w2p, g_w2);

    const int A_ELEM = BL * 512;
    const int W_ELEM = G3 * 512;

    // ---- layer 0 ----
    convert_split<<<A_ELEM / 1024, 256>>>(x, a2p, A_ELEM);
    convert_split<<<W_ELEM / 1024, 256>>>(w_ih_l0,  w2p,                     W_ELEM);
    convert_split<<<W_ELEM / 1024, 256>>>(w_ih_l0r, w2p + (size_t)G3 * 1024, W_ELEM);
    gemm_mma<<<(BL / 128) * 12, 256, GT_SMEM>>>(b_ih_l0, b_ih_l0r);
    gru_cluster<<<128, 256, GRU_SMEM_BYTES>>>(w_hh_l0, w_hh_l0r, b_hh_l0, b_hh_l0r, 0);
    // layer-0 recurrence wrote split-fp16 g_a2 directly (no convert needed)

    // ---- layer 1 ----
    convert_split<<<W_ELEM / 1024, 256>>>(w_ih_l1,  w2p,                     W_ELEM);
    convert_split<<<W_ELEM / 1024, 256>>>(w_ih_l1r, w2p + (size_t)G3 * 1024, W_ELEM);
    gemm_mma<<<(BL / 128) * 12, 256, GT_SMEM>>>(b_ih_l1, b_ih_l1r);
    gru_cluster<<<128, 256, GRU_SMEM_BYTES>>>(w_hh_l1, w_hh_l1r, b_hh_l1, b_hh_l1r, 1);

    // ---- heads ----
    fc_heads<<<BL / 8, 256>>>(fc1_w, fc1_b, fc2_w, fc2_b, y, y2);
    softmax_y_kernel<<<BATCH, 256>>>(y);
    softmax_y2_kernel<<<BATCH, 256>>>(y2, y3);
}

// round 13
// speedup vs baseline: 3.0745x; 1.0280x over previous
#include <cuda_runtime.h>
#include <cuda_bf16.h>
#include <cuda_fp16.h>
#include <math.h>

// Problem constants
#define BATCH 256
#define SEQL  200
#define INF   512
#define HID   256
#define G3    768
#define BL    (BATCH*SEQL)   // 51200

// ---------------- scratch (device globals) -----------------------------------
__device__ float g_xi_f[(size_t)BL * G3];
__device__ float g_xi_r[(size_t)BL * G3];
__device__ float g_seq1[(size_t)BL * 512];
__device__ float g_p[BL];
__device__ __half g_a2[(size_t)BL * 1024];       // A split fp16: [row][hi(512)|lo(512)]
__device__ __half g_w2[2ull * G3 * 1024];        // W split fp16 per dir

// ---------------- helpers -----------------------------------------------------
__device__ __forceinline__ unsigned smem_u32(const void* p) {
    unsigned r;
    asm("{ .reg .u64 t; cvta.to.shared.u64 t, %1; cvt.u32.u64 %0, t; }"
        : "=r"(r) : "l"(p));
    return r;
}
__device__ __forceinline__ unsigned mapa_sh(unsigned addr, unsigned rank) {
    unsigned r;
    asm("mapa.shared::cluster.u32 %0, %1, %2;" : "=r"(r) : "r"(addr), "r"(rank));
    return r;
}
__device__ __forceinline__ void st_cluster_u32(unsigned addr, unsigned v) {
    asm volatile("st.shared::cluster.u32 [%0], %1;" :: "r"(addr), "r"(v) : "memory");
}
__device__ __forceinline__ void cluster_arrive() {
    asm volatile("barrier.cluster.arrive.aligned;" ::: "memory");
}
__device__ __forceinline__ void cluster_wait() {
    asm volatile("barrier.cluster.wait.aligned;" ::: "memory");
}
__device__ __forceinline__ void cluster_sync_full() {
    cluster_arrive(); cluster_wait();
}
__device__ __forceinline__ unsigned ctarank() {
    unsigned r;
    asm("mov.u32 %0, %%cluster_ctarank;" : "=r"(r));
    return r;
}
__device__ __forceinline__ float sigmoid_f(float x) {
    return __fdividef(1.f, 1.f + __expf(-x));
}
__device__ __forceinline__ float tanh_f(float x) {
    return 1.f - __fdividef(2.f, __expf(2.f * x) + 1.f);
}
__device__ __forceinline__ void cp_async16(unsigned sdst, const void* gsrc) {
    asm volatile("cp.async.cg.shared.global [%0], [%1], 16;"
                 :: "r"(sdst), "l"(gsrc) : "memory");
}
#define CP_COMMIT()  asm volatile("cp.async.commit_group;" ::: "memory")
#define CP_WAIT(n)   asm volatile("cp.async.wait_group %0;" :: "n"(n) : "memory")
#define SWZ(o) ((o) ^ (((o) >> 3) & 0x70))

__device__ __forceinline__ void ldsm_x4(unsigned* r, unsigned addr) {
    asm volatile("ldmatrix.sync.aligned.m8n8.x4.shared.b16 {%0,%1,%2,%3}, [%4];"
                 : "=r"(r[0]), "=r"(r[1]), "=r"(r[2]), "=r"(r[3]) : "r"(addr));
}
// fp16 MMA (GEMM path)
__device__ __forceinline__ void mma_f16(float* c, const unsigned* a, const unsigned* b) {
    asm volatile("mma.sync.aligned.m16n8k16.row.col.f32.f16.f16.f32 "
                 "{%0,%1,%2,%3}, {%4,%5,%6,%7}, {%8,%9}, {%0,%1,%2,%3};"
                 : "+f"(c[0]), "+f"(c[1]), "+f"(c[2]), "+f"(c[3])
                 : "r"(a[0]), "r"(a[1]), "r"(a[2]), "r"(a[3]),
                   "r"(b[0]), "r"(b[1]));
}
// bf16 MMA (recurrence path)
__device__ __forceinline__ void mma_bf16(float* c, const unsigned* a, const unsigned* b) {
    asm volatile("mma.sync.aligned.m16n8k16.row.col.f32.bf16.bf16.f32 "
                 "{%0,%1,%2,%3}, {%4,%5,%6,%7}, {%8,%9}, {%0,%1,%2,%3};"
                 : "+f"(c[0]), "+f"(c[1]), "+f"(c[2]), "+f"(c[3])
                 : "r"(a[0]), "r"(a[1]), "r"(a[2]), "r"(a[3]),
                   "r"(b[0]), "r"(b[1]));
}
__device__ __forceinline__ unsigned pack_bf16(float a, float b) {
    __nv_bfloat162 t = __floats2bfloat162_rn(a, b);
    return *(unsigned*)&t;
}
__device__ __forceinline__ unsigned pack_f16(float a, float b) {
    __half2 t = __floats2half2_rn(a, b);
    return *(unsigned*)&t;
}

// ---------------- split-fp16 conversion: src[rows,512] -> dst[rows, hi|lo] ----
__global__ __launch_bounds__(256) void convert_split(
    const float* __restrict__ src, __half* __restrict__ dst, int nelem)
{
    const int idx = (blockIdx.x * 256 + threadIdx.x) * 4;
    if (idx >= nelem) return;
    const int row = idx >> 9, col = idx & 511;
    const float4 v = *(const float4*)(src + idx);
    const __half h0 = __float2half_rn(v.x), h1 = __float2half_rn(v.y);
    const __half h2 = __float2half_rn(v.z), h3 = __float2half_rn(v.w);
    const __half l0 = __float2half_rn(v.x - __half2float(h0));
    const __half l1 = __float2half_rn(v.y - __half2float(h1));
    const __half l2 = __float2half_rn(v.z - __half2float(h2));
    const __half l3 = __float2half_rn(v.w - __half2float(h3));
    __half2* dh = (__half2*)(dst + (size_t)row * 1024 + col);
    __half2* dl = (__half2*)(dst + (size_t)row * 1024 + 512 + col);
    dh[0] = __half2(h0, h1); dh[1] = __half2(h2, h3);
    dl[0] = __half2(l0, l1); dl[1] = __half2(l2, l3);
}

// ---------------- HMMA GEMM: xi = A @ W^T + b (fp16 2-term split) --------------
// K_eff = 1024, 16 chunks of 64. 3-stage cp.async ring, ONE syncthreads/chunk
// (wait c -> sync -> load c+2 overwrites c-1's buffer -> compute c).
// B fragments via paired ldmatrix.x4 (2 n-tiles per instruction).
#define GT_SMEM (3 * 32768 + 1024)
__global__ __launch_bounds__(256) void gemm_mma(
    const float* __restrict__ bf_, const float* __restrict__ br_)
{
    extern __shared__ char dsm[];
    __shared__ float sbias[128];
    const unsigned sbase = (smem_u32(dsm) + 1023u) & ~1023u;

    const int tid = threadIdx.x;
    const int wid = tid >> 5, lane = tid & 31;
    const int wm = wid >> 2, wn = wid & 3;
    const int g = lane >> 2, tig = lane & 3;

    const int bx = blockIdx.x;
    const int m_tile = bx / 12;
    const int sub = bx - m_tile * 12;
    const int dir = sub >= 6;
    const int n0 = (dir ? sub - 6 : sub) * 128;
    const int m0 = m_tile * 128;
    float* C = dir ? g_xi_r : g_xi_f;
    const __half* w2 = g_w2 + (size_t)dir * G3 * 1024;
    const float* bias = dir ? br_ : bf_;

    if (tid < 128) sbias[tid] = bias[n0 + tid];

    // A fragment addressing (x4, 16 rows x 16 k)
    const int arow = wm * 64 + (lane & 15);
    const unsigned axm = (unsigned)(arow & 7) * 16u;
    const unsigned acol8 = (unsigned)(lane >> 4) * 16u;
    // B fragment addressing (paired x4: rows {n..n+7, n+8..n+15} x 16 k)
    const int brow4 = wn * 32 + (lane & 7) + ((lane >> 4) & 1) * 8;
    const unsigned bxm4 = (unsigned)(lane & 7) * 16u;   // (row&7) same for both halves
    const unsigned bcol4 = (unsigned)((lane >> 3) & 1) * 16u;

    float acc[4][4][4];
#pragma unroll
    for (int mt = 0; mt < 4; mt++)
#pragma unroll
        for (int nt = 0; nt < 4; nt++)
#pragma unroll
            for (int q = 0; q < 4; q++) acc[mt][nt][q] = 0.f;

    const int lrow = tid & 127;
    const int isb = tid >> 7;
    auto load_chunk = [&](int c, int buf) {
        int acol, bcol;
        if (c < 8) { acol = c * 64;             bcol = c * 64; }        // ah*bh
        else       { acol = 512 + (c - 8) * 64; bcol = (c - 8) * 64; }  // al*bh
        const __half* src = isb
            ? (w2 + (size_t)(n0 + lrow) * 1024 + bcol)
            : (g_a2 + (size_t)(m0 + lrow) * 1024 + acol);
        const unsigned dbuf = sbase + (unsigned)buf * 32768u + (unsigned)isb * 16384u;
        const unsigned rowo = (unsigned)lrow * 128u;
#pragma unroll
        for (int q = 0; q < 8; q++)
            cp_async16(dbuf + SWZ(rowo + q * 16u), src + q * 8);
        CP_COMMIT();
    };

    load_chunk(0, 0);
    load_chunk(1, 1);

    int buf = 0;
    for (int c = 0; c < 16; c++) {
        if (c < 15) { CP_WAIT(1); } else { CP_WAIT(0); }
        __syncthreads();          // chunk c visible to all; compute c-1 retired
        if (c + 2 < 16) {
            int nb = buf + 2; if (nb >= 3) nb -= 3;
            load_chunk(c + 2, nb);   // overwrites c-1's buffer (safe)
        }

        const unsigned abuf = sbase + (unsigned)buf * 32768u;
        const unsigned bbuf = abuf + 16384u;
#pragma unroll
        for (int ks = 0; ks < 4; ks++) {
            const unsigned akc = (unsigned)(ks * 32) + acol8;
            const unsigned bkc = (unsigned)(ks * 32) + bcol4;
            unsigned af[4][4];
#pragma unroll
            for (int mt = 0; mt < 4; mt++)
                ldsm_x4(af[mt], abuf + (unsigned)(arow + mt * 16) * 128u + (akc ^ axm));
            unsigned bfr[2][4];   // [nt-pair][4 regs: nt frag (0,1), nt+1 frag (2,3)]
#pragma unroll
            for (int np = 0; np < 2; np++)
                ldsm_x4(bfr[np],
                        bbuf + (unsigned)(brow4 + np * 16) * 128u + (bkc ^ bxm4));
#pragma unroll
            for (int mt = 0; mt < 4; mt++)
#pragma unroll
                for (int np = 0; np < 2; np++) {
                    mma_f16(acc[mt][2 * np + 0], af[mt], &bfr[np][0]);
                    mma_f16(acc[mt][2 * np + 1], af[mt], &bfr[np][2]);
                }
        }
        buf++; if (buf >= 3) buf -= 3;
    }

#pragma unroll
    for (int mt = 0; mt < 4; mt++) {
        const int m = m0 + wm * 64 + mt * 16 + g;
#pragma unroll
        for (int nt = 0; nt < 4; nt++) {
            const int nloc = wn * 32 + nt * 8 + 2 * tig;
            const float b0 = sbias[nloc], b1 = sbias[nloc + 1];
            float2 v0, v1;
            v0.x = acc[mt][nt][0] + b0; v0.y = acc[mt][nt][1] + b1;
            v1.x = acc[mt][nt][2] + b0; v1.y = acc[mt][nt][3] + b1;
            *(float2*)(C + (size_t)m * G3 + n0 + nloc) = v0;
            *(float2*)(C + (size_t)(m + 8) * G3 + n0 + nloc) = v1;
        }
    }
}

// ---------------- cluster-persistent GRU recurrence (unchanged R11/R12) -------
#define RW_HI    0u
#define RW_LO    98304u
#define RA_BASE  196608u      // two buffers of 16KB (hi 8KB + lo 8KB)
#define GRU_SMEM_BYTES 229376u

__global__ void __launch_bounds__(256, 1) __cluster_dims__(4, 1, 1)
gru_cluster(const float* __restrict__ whh_f, const float* __restrict__ whh_r,
            const float* __restrict__ bhh_f, const float* __restrict__ bhh_r,
            int layer)
{
    extern __shared__ char rsm[];
    const unsigned sb = smem_u32(rsm);

    const unsigned rank = ctarank();
    const int cid = blockIdx.x >> 2;
    const int dir = cid >> 4;
    const int bg  = cid & 15;

    const float* xi  = dir ? g_xi_r : g_xi_f;
    const float* whh = dir ? whh_r : whh_f;
    const float* bhh = dir ? bhh_r : bhh_f;
    const int zoff = dir * HID;

    const int tid = threadIdx.x;
    const int w = tid >> 5, lane = tid & 31;

    if (tid < 192) {
        const int n = tid;
        const int gg = n >> 6, hl = n & 63;
        const float* wrow = whh + (size_t)(gg * HID + rank * 64 + hl) * HID;
        const unsigned xm = (unsigned)(n & 7) * 16u;
#pragma unroll 4
        for (int kk = 0; kk < 128; kk++) {
            const float2 v = *(const float2*)(wrow + 2 * kk);
            const float h0f = __bfloat162float(__float2bfloat16(v.x));
            const float h1f = __bfloat162float(__float2bfloat16(v.y));
            const unsigned off = ((unsigned)(kk * 4)) ^ xm;
            *(unsigned*)(rsm + (unsigned)n * 512u + RW_HI + off) = pack_bf16(v.x, v.y);
            *(unsigned*)(rsm + (unsigned)n * 512u + RW_LO + off) =
                pack_bf16(v.x - h0f, v.y - h1f);
        }
    }
    for (unsigned i = tid; i < 8192; i += 256)
        *(unsigned*)(rsm + RA_BASE + i * 4) = 0u;
    __syncthreads();
    cluster_sync_full();

    const int hl2 = w * 8 + (lane & 3) * 2;
    const int hg0 = rank * 64 + hl2;
    const int b0 = lane >> 2;
    const float2 br2 = *(const float2*)(bhh + hg0);
    const float2 bz2 = *(const float2*)(bhh + HID + hg0);
    const float2 bn2 = *(const float2*)(bhh + 2 * HID + hg0);

    const unsigned arow_off = (unsigned)(lane & 15) * 512u;
    const unsigned axor = (unsigned)((lane & 15) & 7) * 16u;
    const unsigned acol = (unsigned)(lane >> 4) * 16u;
    const unsigned bxor = (unsigned)(lane & 7) * 16u;
    const unsigned bcol = (unsigned)(lane >> 3) * 16u;
    unsigned wrow_off[3];
#pragma unroll
    for (int gg = 0; gg < 3; gg++)
        wrow_off[gg] = (unsigned)((gg * 64 + w * 8 + (lane & 7)) * 512);

    const unsigned xw0 = (unsigned)(b0 & 7) * 16u;
    const unsigned xw1 = (unsigned)((b0 + 8) & 7) * 16u;
    const unsigned relH0 = (unsigned)b0 * 512u + (((unsigned)(2 * hg0)) ^ xw0);
    const unsigned relH1 = (unsigned)(b0 + 8) * 512u + (((unsigned)(2 * hg0)) ^ xw1);
    unsigned rmap[4];
#pragma unroll
    for (unsigned r = 0; r < 4; r++) rmap[r] = mapa_sh(sb, r);

    float2 xig[3][2];
    {
        const int t0 = dir ? (SEQL - 1) : 0;
        const float* xp0 = xi + ((size_t)(bg * 16 + b0) * SEQL + t0) * G3 + hg0;
        const float* xp1 = xi + ((size_t)(bg * 16 + b0 + 8) * SEQL + t0) * G3 + hg0;
#pragma unroll
        for (int gg = 0; gg < 3; gg++) {
            xig[gg][0] = *(const float2*)(xp0 + gg * HID);
            xig[gg][1] = *(const float2*)(xp1 + gg * HID);
        }
    }

    for (int s = 0; s < SEQL; s++) {
        const int t = dir ? (SEQL - 1 - s) : s;
        const unsigned rdb = RA_BASE + (unsigned)(s & 1) * 16384u;
        const unsigned wrb = RA_BASE + (unsigned)((s + 1) & 1) * 16384u;

        float acc[3][4];
#pragma unroll
        for (int gg = 0; gg < 3; gg++)
#pragma unroll
            for (int q = 0; q < 4; q++) acc[gg][q] = 0.f;

#pragma unroll
        for (int term = 0; term < 3; term++) {
            const unsigned Ab = sb + rdb + ((term == 1) ? 8192u : 0u);
            const unsigned Wb = sb + ((term == 2) ? RW_LO : RW_HI);
#pragma unroll
            for (int ks2 = 0; ks2 < 8; ks2++) {
                const unsigned k0b = (unsigned)(ks2 * 64);
                unsigned af0[4], af1[4];
                ldsm_x4(af0, Ab + arow_off + ((k0b + acol) ^ axor));
                ldsm_x4(af1, Ab + arow_off + ((k0b + 32u + acol) ^ axor));
#pragma unroll
                for (int gg = 0; gg < 3; gg++) {
                    unsigned bfr[4];
                    ldsm_x4(bfr, Wb + wrow_off[gg] + ((k0b + bcol) ^ bxor));
                    mma_bf16(acc[gg], af0, bfr);
                    mma_bf16(acc[gg], af1, bfr + 2);
                }
            }
        }

        float hp[2][2];
        {
            const __nv_bfloat162 h0w = *(const __nv_bfloat162*)(rsm + rdb + relH0);
            const __nv_bfloat162 l0w = *(const __nv_bfloat162*)(rsm + rdb + 8192u + relH0);
            const __nv_bfloat162 h1w = *(const __nv_bfloat162*)(rsm + rdb + relH1);
            const __nv_bfloat162 l1w = *(const __nv_bfloat162*)(rsm + rdb + 8192u + relH1);
            hp[0][0] = __bfloat162float(h0w.x) + __bfloat162float(l0w.x);
            hp[0][1] = __bfloat162float(h0w.y) + __bfloat162float(l0w.y);
            hp[1][0] = __bfloat162float(h1w.x) + __bfloat162float(l1w.x);
            hp[1][1] = __bfloat162float(h1w.y) + __bfloat162float(l1w.y);
        }

        float hnew[2][2];
#pragma unroll
        for (int bi = 0; bi < 2; bi++) {
#pragma unroll
            for (int hj = 0; hj < 2; hj++) {
                const int q = bi * 2 + hj;
                const float gr = acc[0][q] + (hj ? br2.y : br2.x);
                const float gz = acc[1][q] + (hj ? bz2.y : bz2.x);
                const float gn = acc[2][q] + (hj ? bn2.y : bn2.x);
                const float xr = hj ? xig[0][bi].y : xig[0][bi].x;
                const float xz = hj ? xig[1][bi].y : xig[1][bi].x;
                const float xn = hj ? xig[2][bi].y : xig[2][bi].x;
                const float rg = sigmoid_f(xr + gr);
                const float zg = sigmoid_f(xz + gz);
                const float ng = tanh_f(xn + rg * gn);
                hnew[bi][hj] = (1.f - zg) * ng + zg * hp[bi][hj];
            }
        }

        unsigned whw[2], wlw[2];
#pragma unroll
        for (int bi = 0; bi < 2; bi++) {
            const float r0 = __bfloat162float(__float2bfloat16(hnew[bi][0]));
            const float r1 = __bfloat162float(__float2bfloat16(hnew[bi][1]));
            whw[bi] = pack_bf16(hnew[bi][0], hnew[bi][1]);
            wlw[bi] = pack_bf16(hnew[bi][0] - r0, hnew[bi][1] - r1);
        }

#pragma unroll
        for (int bi = 0; bi < 2; bi++) {
            const int b = bg * 16 + b0 + bi * 8;
            const size_t row = (size_t)b * SEQL + t;
            if (layer) {
                *(float2*)(g_seq1 + row * 512 + zoff + hg0) =
                    make_float2(hnew[bi][0], hnew[bi][1]);
            } else {
                const float f0 = __half2float(__float2half_rn(hnew[bi][0]));
                const float f1 = __half2float(__float2half_rn(hnew[bi][1]));
                *(unsigned*)&g_a2[row * 1024 + zoff + hg0] =
                    pack_f16(hnew[bi][0], hnew[bi][1]);
                *(unsigned*)&g_a2[row * 1024 + 512 + zoff + hg0] =
                    pack_f16(hnew[bi][0] - f0, hnew[bi][1] - f1);
            }
        }

#pragma unroll
        for (unsigned r = 0; r < 4; r++) {
            st_cluster_u32(rmap[r] + wrb + relH0, whw[0]);
            st_cluster_u32(rmap[r] + wrb + 8192u + relH0, wlw[0]);
            st_cluster_u32(rmap[r] + wrb + relH1, whw[1]);
            st_cluster_u32(rmap[r] + wrb + 8192u + relH1, wlw[1]);
        }

        cluster_arrive();

        if (s + 1 < SEQL) {
            const int tn_ = dir ? (SEQL - 2 - s) : (s + 1);
            const float* xp0 = xi + ((size_t)(bg * 16 + b0) * SEQL + tn_) * G3 + hg0;
            const float* xp1 = xi + ((size_t)(bg * 16 + b0 + 8) * SEQL + tn_) * G3 + hg0;
#pragma unroll
            for (int gg = 0; gg < 3; gg++) {
                xig[gg][0] = *(const float2*)(xp0 + gg * HID);
                xig[gg][1] = *(const float2*)(xp1 + gg * HID);
            }
        }

        cluster_wait();
    }
}

// ---------------- heads: warp-per-row ------------------------------------------
__global__ __launch_bounds__(256) void fc_heads(
    const float* __restrict__ fc1w, const float* __restrict__ fc1b,
    const float* __restrict__ fc2w, const float* __restrict__ fc2b,
    float* __restrict__ y, float* __restrict__ y2)
{
    __shared__ float ws[11 * 512];
    __shared__ float bsh[11];
    const int tid = threadIdx.x;
    for (int i = tid; i < 5120; i += 256) ws[i] = fc2w[i];
    for (int i = tid; i < 512; i += 256) ws[5120 + i] = fc1w[i];
    if (tid < 10) bsh[tid] = fc2b[tid];
    if (tid == 10) bsh[10] = fc1b[0];
    __syncthreads();

    const int wid = tid >> 5, lane = tid & 31;
    const int bt = blockIdx.x * 8 + wid;
    const float4* row = (const float4*)(g_seq1 + (size_t)bt * 512);
    float4 v[4];
#pragma unroll
    for (int q = 0; q < 4; q++) v[q] = row[q * 32 + lane];

#pragma unroll
    for (int j = 0; j < 11; j++) {
        const float4* wj = (const float4*)(ws + j * 512);
        float s = 0.f;
#pragma unroll
        for (int q = 0; q < 4; q++) {
            const float4 wv = wj[q * 32 + lane];
            s += v[q].x * wv.x + v[q].y * wv.y + v[q].z * wv.z + v[q].w * wv.w;
        }
#pragma unroll
        for (int off = 16; off; off >>= 1) s += __shfl_xor_sync(0xffffffffu, s, off);
        if (lane == 0) {
            if (j < 10) y2[(size_t)bt * 10 + j] = s + bsh[j];
            else        y[bt] = s + bsh[10];
        }
    }
}

__global__ __launch_bounds__(256) void softmax_y_kernel(const float* __restrict__ y) {
    const int b = blockIdx.x;
    __shared__ float sh[256];
    const int tid = threadIdx.x;
    float v = (tid < SEQL) ? y[b * SEQL + tid] : -INFINITY;
    sh[tid] = v; __syncthreads();
    for (int s = 128; s; s >>= 1) {
        if (tid < s) sh[tid] = fmaxf(sh[tid], sh[tid + s]);
        __syncthreads();
    }
    const float mx = sh[0]; __syncthreads();
    const float e = (tid < SEQL) ? __expf(v - mx) : 0.f;
    sh[tid] = e; __syncthreads();
    for (int s = 128; s; s >>= 1) {
        if (tid < s) sh[tid] += sh[tid + s];
        __syncthreads();
    }
    const float inv = 1.f / sh[0];
    if (tid < SEQL) g_p[b * SEQL + tid] = e * inv * 0.1f;
}

__global__ __launch_bounds__(256) void softmax_y2_kernel(
    const float* __restrict__ y2, float* __restrict__ y3)
{
    const int b = blockIdx.x;
    const int tid = threadIdx.x;
    __shared__ float sh[256];
    const float* src = y2 + (size_t)b * 2000;
    float mx = -INFINITY;
    for (int i = tid; i < 2000; i += 256) mx = fmaxf(mx, src[i]);
    sh[tid] = mx; __syncthreads();
    for (int s = 128; s; s >>= 1) {
        if (tid < s) sh[tid] = fmaxf(sh[tid], sh[tid + s]);
        __syncthreads();
    }
    mx = sh[0]; __syncthreads();
    float sum = 0.f;
    for (int i = tid; i < 2000; i += 256) sum += __expf(src[i] - mx);
    sh[tid] = sum; __syncthreads();
    for (int s = 128; s; s >>= 1) {
        if (tid < s) sh[tid] += sh[tid + s];
        __syncthreads();
    }
    const float inv = 1.f / sh[0];
    for (int i = tid; i < 2000; i += 256)
        y3[(size_t)b * 2000 + i] = __expf(src[i] - mx) * inv + g_p[b * SEQL + i / 10];
}

// ---------------- driver ------------------------------------------------------
extern "C" void kernel_launch(void* const* d_in, const int* in_sizes, int n_in,
                              void* d_out, int out_size) {
    (void)in_sizes; (void)n_in; (void)out_size;
    const float* x        = (const float*)d_in[0];
    const float* w_ih_l0  = (const float*)d_in[1];
    const float* w_hh_l0  = (const float*)d_in[2];
    const float* b_ih_l0  = (const float*)d_in[3];
    const float* b_hh_l0  = (const float*)d_in[4];
    const float* w_ih_l0r = (const float*)d_in[5];
    const float* w_hh_l0r = (const float*)d_in[6];
    const float* b_ih_l0r = (const float*)d_in[7];
    const float* b_hh_l0r = (const float*)d_in[8];
    const float* w_ih_l1  = (const float*)d_in[9];
    const float* w_hh_l1  = (const float*)d_in[10];
    const float* b_ih_l1  = (const float*)d_in[11];
    const float* b_hh_l1  = (const float*)d_in[12];
    const float* w_ih_l1r = (const float*)d_in[13];
    const float* w_hh_l1r = (const float*)d_in[14];
    const float* b_ih_l1r = (const float*)d_in[15];
    const float* b_hh_l1r = (const float*)d_in[16];
    const float* fc1_w    = (const float*)d_in[17];
    const float* fc1_b    = (const float*)d_in[18];
    const float* fc2_w    = (const float*)d_in[19];
    const float* fc2_b    = (const float*)d_in[20];

    float* y  = (float*)d_out;
    float* y2 = y + BL;
    float* y3 = y2 + BL * 10;

    static int configured = 0;
    if (!configured) {
        cudaFuncSetAttribute(gru_cluster, cudaFuncAttributeMaxDynamicSharedMemorySize,
                             GRU_SMEM_BYTES);
        cudaFuncSetAttribute(gemm_mma, cudaFuncAttributeMaxDynamicSharedMemorySize,
                             GT_SMEM);
        configured = 1;
    }

    __half* a2p = nullptr;
    __half* w2p = nullptr;
    cudaGetSymbolAddress((void**)&a2p, g_a2);
    cudaGetSymbolAddress((void**)&w2p, g_w2);

    const int A_ELEM = BL * 512;
    const int W_ELEM = G3 * 512;

    // ---- layer 0 ----
    convert_split<<<A_ELEM / 1024, 256>>>(x, a2p, A_ELEM);
    convert_split<<<W_ELEM / 1024, 256>>>(w_ih_l0,  w2p,                     W_ELEM);
    convert_split<<<W_ELEM / 1024, 256>>>(w_ih_l0r, w2p + (size_t)G3 * 1024, W_ELEM);
    gemm_mma<<<(BL / 128) * 12, 256, GT_SMEM>>>(b_ih_l0, b_ih_l0r);
    gru_cluster<<<128, 256, GRU_SMEM_BYTES>>>(w_hh_l0, w_hh_l0r, b_hh_l0, b_hh_l0r, 0);
    // layer-0 recurrence wrote split-fp16 g_a2 directly (no convert needed)

    // ---- layer 1 ----
    convert_split<<<W_ELEM / 1024, 256>>>(w_ih_l1,  w2p,                     W_ELEM);
    convert_split<<<W_ELEM / 1024, 256>>>(w_ih_l1r, w2p + (size_t)G3 * 1024, W_ELEM);
    gemm_mma<<<(BL / 128) * 12, 256, GT_SMEM>>>(b_ih_l1, b_ih_l1r);
    gru_cluster<<<128, 256, GRU_SMEM_BYTES>>>(w_hh_l1, w_hh_l1r, b_hh_l1, b_hh_l1r, 1);

    // ---- heads ----
    fc_heads<<<BL / 8, 256>>>(fc1_w, fc1_b, fc2_w, fc2_b, y, y2);
    softmax_y_kernel<<<BATCH, 256>>>(y);
    softmax_y2_kernel<<<BATCH, 256>>>(y2, y3);
}

// round 14
// speedup vs baseline: 3.3532x; 1.0907x over previous
#include <cuda_runtime.h>
#include <cuda_bf16.h>
#include <cuda_fp16.h>
#include <math.h>

// Problem constants
#define BATCH 256
#define SEQL  200
#define INF   512
#define HID   256
#define G3    768
#define BL    (BATCH*SEQL)   // 51200

// ---------------- scratch (device globals) -----------------------------------
__device__ float g_xi_f[(size_t)BL * G3];
__device__ float g_xi_r[(size_t)BL * G3];
__device__ float g_seq1[(size_t)BL * 512];
__device__ float g_p[BL];
__device__ __half g_a2[(size_t)BL * 1024];       // A split fp16: [row][hi(512)|lo(512)]
__device__ __half g_w2[2ull * G3 * 1024];        // W split fp16 per dir (hi used)

// ---------------- helpers -----------------------------------------------------
__device__ __forceinline__ unsigned smem_u32(const void* p) {
    unsigned r;
    asm("{ .reg .u64 t; cvta.to.shared.u64 t, %1; cvt.u32.u64 %0, t; }"
        : "=r"(r) : "l"(p));
    return r;
}
__device__ __forceinline__ unsigned mapa_sh(unsigned addr, unsigned rank) {
    unsigned r;
    asm("mapa.shared::cluster.u32 %0, %1, %2;" : "=r"(r) : "r"(addr), "r"(rank));
    return r;
}
__device__ __forceinline__ void st_cluster_u32(unsigned addr, unsigned v) {
    asm volatile("st.shared::cluster.u32 [%0], %1;" :: "r"(addr), "r"(v) : "memory");
}
__device__ __forceinline__ void cluster_arrive() {
    asm volatile("barrier.cluster.arrive.aligned;" ::: "memory");
}
__device__ __forceinline__ void cluster_wait() {
    asm volatile("barrier.cluster.wait.aligned;" ::: "memory");
}
__device__ __forceinline__ void cluster_sync_full() {
    cluster_arrive(); cluster_wait();
}
__device__ __forceinline__ unsigned ctarank() {
    unsigned r;
    asm("mov.u32 %0, %%cluster_ctarank;" : "=r"(r));
    return r;
}
__device__ __forceinline__ float sigmoid_f(float x) {
    return __fdividef(1.f, 1.f + __expf(-x));
}
__device__ __forceinline__ float tanh_f(float x) {
    return 1.f - __fdividef(2.f, __expf(2.f * x) + 1.f);
}
__device__ __forceinline__ void cp_async16(unsigned sdst, const void* gsrc) {
    asm volatile("cp.async.cg.shared.global [%0], [%1], 16;"
                 :: "r"(sdst), "l"(gsrc) : "memory");
}
#define CP_COMMIT()  asm volatile("cp.async.commit_group;" ::: "memory")
#define CP_WAIT(n)   asm volatile("cp.async.wait_group %0;" :: "n"(n) : "memory")
#define SWZ(o) ((o) ^ (((o) >> 3) & 0x70))

__device__ __forceinline__ void ldsm_x4(unsigned* r, unsigned addr) {
    asm volatile("ldmatrix.sync.aligned.m8n8.x4.shared.b16 {%0,%1,%2,%3}, [%4];"
                 : "=r"(r[0]), "=r"(r[1]), "=r"(r[2]), "=r"(r[3]) : "r"(addr));
}
// fp16 MMA (GEMM path)
__device__ __forceinline__ void mma_f16(float* c, const unsigned* a, const unsigned* b) {
    asm volatile("mma.sync.aligned.m16n8k16.row.col.f32.f16.f16.f32 "
                 "{%0,%1,%2,%3}, {%4,%5,%6,%7}, {%8,%9}, {%0,%1,%2,%3};"
                 : "+f"(c[0]), "+f"(c[1]), "+f"(c[2]), "+f"(c[3])
                 : "r"(a[0]), "r"(a[1]), "r"(a[2]), "r"(a[3]),
                   "r"(b[0]), "r"(b[1]));
}
// bf16 MMA (recurrence path)
__device__ __forceinline__ void mma_bf16(float* c, const unsigned* a, const unsigned* b) {
    asm volatile("mma.sync.aligned.m16n8k16.row.col.f32.bf16.bf16.f32 "
                 "{%0,%1,%2,%3}, {%4,%5,%6,%7}, {%8,%9}, {%0,%1,%2,%3};"
                 : "+f"(c[0]), "+f"(c[1]), "+f"(c[2]), "+f"(c[3])
                 : "r"(a[0]), "r"(a[1]), "r"(a[2]), "r"(a[3]),
                   "r"(b[0]), "r"(b[1]));
}
__device__ __forceinline__ unsigned pack_bf16(float a, float b) {
    __nv_bfloat162 t = __floats2bfloat162_rn(a, b);
    return *(unsigned*)&t;
}
__device__ __forceinline__ unsigned pack_f16(float a, float b) {
    __half2 t = __floats2half2_rn(a, b);
    return *(unsigned*)&t;
}

// ---------------- split-fp16 conversion: src[rows,512] -> dst[rows, hi|lo] ----
__global__ __launch_bounds__(256) void convert_split(
    const float* __restrict__ src, __half* __restrict__ dst, int nelem)
{
    const int idx = (blockIdx.x * 256 + threadIdx.x) * 4;
    if (idx >= nelem) return;
    const int row = idx >> 9, col = idx & 511;
    const float4 v = *(const float4*)(src + idx);
    const __half h0 = __float2half_rn(v.x), h1 = __float2half_rn(v.y);
    const __half h2 = __float2half_rn(v.z), h3 = __float2half_rn(v.w);
    const __half l0 = __float2half_rn(v.x - __half2float(h0));
    const __half l1 = __float2half_rn(v.y - __half2float(h1));
    const __half l2 = __float2half_rn(v.z - __half2float(h2));
    const __half l3 = __float2half_rn(v.w - __half2float(h3));
    __half2* dh = (__half2*)(dst + (size_t)row * 1024 + col);
    __half2* dl = (__half2*)(dst + (size_t)row * 1024 + 512 + col);
    dh[0] = __half2(h0, h1); dh[1] = __half2(h2, h3);
    dl[0] = __half2(l0, l1); dl[1] = __half2(l2, l3);
}

// ---------------- HMMA GEMM: xi = A @ W^T + b (fp16 2-term, shared-B chunks) ---
// 8 chunks of k=64. Each chunk stages Ah | Al | B (48KB); per kstep the B
// fragments are loaded ONCE and used for both the ah*bh and al*bh terms (af
// registers reloaded hi->lo). Halves chunk count (syncs) and B L2 traffic.
#define GST 49152u                     // stage size: Ah 16K | Al 16K | B 16K
#define GT_SMEM (2 * 49152 + 1024)
__global__ __launch_bounds__(256) void gemm_mma(
    const float* __restrict__ bf_, const float* __restrict__ br_)
{
    extern __shared__ char dsm[];
    __shared__ float sbias[128];
    const unsigned sbase = (smem_u32(dsm) + 1023u) & ~1023u;

    const int tid = threadIdx.x;
    const int wid = tid >> 5, lane = tid & 31;
    const int wm = wid >> 2, wn = wid & 3;
    const int g = lane >> 2, tig = lane & 3;

    const int bx = blockIdx.x;
    const int m_tile = bx / 12;
    const int sub = bx - m_tile * 12;
    const int dir = sub >= 6;
    const int n0 = (dir ? sub - 6 : sub) * 128;
    const int m0 = m_tile * 128;
    float* C = dir ? g_xi_r : g_xi_f;
    const __half* w2 = g_w2 + (size_t)dir * G3 * 1024;
    const float* bias = dir ? br_ : bf_;

    if (tid < 128) sbias[tid] = bias[n0 + tid];

    // A fragment addressing (x4, 16 rows x 16 k)
    const int arow = wm * 64 + (lane & 15);
    const unsigned axm = (unsigned)(arow & 7) * 16u;
    const unsigned acol8 = (unsigned)(lane >> 4) * 16u;
    // B fragment addressing (paired x4: rows {n..n+7, n+8..n+15} x 16 k)
    const int brow4 = wn * 32 + (lane & 7) + ((lane >> 4) & 1) * 8;
    const unsigned bxm4 = (unsigned)(lane & 7) * 16u;
    const unsigned bcol4 = (unsigned)((lane >> 3) & 1) * 16u;

    float acc[4][4][4];
#pragma unroll
    for (int mt = 0; mt < 4; mt++)
#pragma unroll
        for (int nt = 0; nt < 4; nt++)
#pragma unroll
            for (int q = 0; q < 4; q++) acc[mt][nt][q] = 0.f;

    const int lrow = tid & 127;
    const int isb = tid >> 7;
    auto load_chunk = [&](int c, int buf) {
        const unsigned stage = sbase + (unsigned)buf * GST;
        const unsigned rowo = (unsigned)lrow * 128u;
        if (isb) {
            // B rows: bh cols c*64
            const __half* src = w2 + (size_t)(n0 + lrow) * 1024 + c * 64;
#pragma unroll
            for (int q = 0; q < 8; q++)
                cp_async16(stage + 32768u + SWZ(rowo + q * 16u), src + q * 8);
        } else {
            // A rows: hi cols c*64, lo cols 512 + c*64
            const __half* srch = g_a2 + (size_t)(m0 + lrow) * 1024 + c * 64;
#pragma unroll
            for (int q = 0; q < 8; q++)
                cp_async16(stage + SWZ(rowo + q * 16u), srch + q * 8);
            const __half* srcl = srch + 512;
#pragma unroll
            for (int q = 0; q < 8; q++)
                cp_async16(stage + 16384u + SWZ(rowo + q * 16u), srcl + q * 8);
        }
        CP_COMMIT();
    };

    load_chunk(0, 0);

    for (int c = 0; c < 8; c++) {
        const int buf = c & 1;
        if (c < 7) { load_chunk(c + 1, (c + 1) & 1); CP_WAIT(1); }
        else       { CP_WAIT(0); }
        __syncthreads();

        const unsigned stage = sbase + (unsigned)buf * GST;
        const unsigned ahbuf = stage;
        const unsigned albuf = stage + 16384u;
        const unsigned bbuf  = stage + 32768u;
#pragma unroll
        for (int ks = 0; ks < 4; ks++) {
            const unsigned akc = (unsigned)(ks * 32) + acol8;
            const unsigned bkc = (unsigned)(ks * 32) + bcol4;
            // B fragments once per kstep (shared by hi and lo terms)
            unsigned bfr[2][4];
#pragma unroll
            for (int np = 0; np < 2; np++)
                ldsm_x4(bfr[np],
                        bbuf + (unsigned)(brow4 + np * 16) * 128u + (bkc ^ bxm4));
            // hi term
            unsigned af[4][4];
#pragma unroll
            for (int mt = 0; mt < 4; mt++)
                ldsm_x4(af[mt], ahbuf + (unsigned)(arow + mt * 16) * 128u + (akc ^ axm));
#pragma unroll
            for (int mt = 0; mt < 4; mt++)
#pragma unroll
                for (int np = 0; np < 2; np++) {
                    mma_f16(acc[mt][2 * np + 0], af[mt], &bfr[np][0]);
                    mma_f16(acc[mt][2 * np + 1], af[mt], &bfr[np][2]);
                }
            // lo term (reuse af registers)
#pragma unroll
            for (int mt = 0; mt < 4; mt++)
                ldsm_x4(af[mt], albuf + (unsigned)(arow + mt * 16) * 128u + (akc ^ axm));
#pragma unroll
            for (int mt = 0; mt < 4; mt++)
#pragma unroll
                for (int np = 0; np < 2; np++) {
                    mma_f16(acc[mt][2 * np + 0], af[mt], &bfr[np][0]);
                    mma_f16(acc[mt][2 * np + 1], af[mt], &bfr[np][2]);
                }
        }
        __syncthreads();
    }

#pragma unroll
    for (int mt = 0; mt < 4; mt++) {
        const int m = m0 + wm * 64 + mt * 16 + g;
#pragma unroll
        for (int nt = 0; nt < 4; nt++) {
            const int nloc = wn * 32 + nt * 8 + 2 * tig;
            const float b0 = sbias[nloc], b1 = sbias[nloc + 1];
            float2 v0, v1;
            v0.x = acc[mt][nt][0] + b0; v0.y = acc[mt][nt][1] + b1;
            v1.x = acc[mt][nt][2] + b0; v1.y = acc[mt][nt][3] + b1;
            *(float2*)(C + (size_t)m * G3 + n0 + nloc) = v0;
            *(float2*)(C + (size_t)(m + 8) * G3 + n0 + nloc) = v1;
        }
    }
}

// ---------------- cluster-persistent GRU recurrence (unchanged R11/R12) -------
#define RW_HI    0u
#define RW_LO    98304u
#define RA_BASE  196608u      // two buffers of 16KB (hi 8KB + lo 8KB)
#define GRU_SMEM_BYTES 229376u

__global__ void __launch_bounds__(256, 1) __cluster_dims__(4, 1, 1)
gru_cluster(const float* __restrict__ whh_f, const float* __restrict__ whh_r,
            const float* __restrict__ bhh_f, const float* __restrict__ bhh_r,
            int layer)
{
    extern __shared__ char rsm[];
    const unsigned sb = smem_u32(rsm);

    const unsigned rank = ctarank();
    const int cid = blockIdx.x >> 2;
    const int dir = cid >> 4;
    const int bg  = cid & 15;

    const float* xi  = dir ? g_xi_r : g_xi_f;
    const float* whh = dir ? whh_r : whh_f;
    const float* bhh = dir ? bhh_r : bhh_f;
    const int zoff = dir * HID;

    const int tid = threadIdx.x;
    const int w = tid >> 5, lane = tid & 31;

    if (tid < 192) {
        const int n = tid;
        const int gg = n >> 6, hl = n & 63;
        const float* wrow = whh + (size_t)(gg * HID + rank * 64 + hl) * HID;
        const unsigned xm = (unsigned)(n & 7) * 16u;
#pragma unroll 4
        for (int kk = 0; kk < 128; kk++) {
            const float2 v = *(const float2*)(wrow + 2 * kk);
            const float h0f = __bfloat162float(__float2bfloat16(v.x));
            const float h1f = __bfloat162float(__float2bfloat16(v.y));
            const unsigned off = ((unsigned)(kk * 4)) ^ xm;
            *(unsigned*)(rsm + (unsigned)n * 512u + RW_HI + off) = pack_bf16(v.x, v.y);
            *(unsigned*)(rsm + (unsigned)n * 512u + RW_LO + off) =
                pack_bf16(v.x - h0f, v.y - h1f);
        }
    }
    for (unsigned i = tid; i < 8192; i += 256)
        *(unsigned*)(rsm + RA_BASE + i * 4) = 0u;
    __syncthreads();
    cluster_sync_full();

    const int hl2 = w * 8 + (lane & 3) * 2;
    const int hg0 = rank * 64 + hl2;
    const int b0 = lane >> 2;
    const float2 br2 = *(const float2*)(bhh + hg0);
    const float2 bz2 = *(const float2*)(bhh + HID + hg0);
    const float2 bn2 = *(const float2*)(bhh + 2 * HID + hg0);

    const unsigned arow_off = (unsigned)(lane & 15) * 512u;
    const unsigned axor = (unsigned)((lane & 15) & 7) * 16u;
    const unsigned acol = (unsigned)(lane >> 4) * 16u;
    const unsigned bxor = (unsigned)(lane & 7) * 16u;
    const unsigned bcol = (unsigned)(lane >> 3) * 16u;
    unsigned wrow_off[3];
#pragma unroll
    for (int gg = 0; gg < 3; gg++)
        wrow_off[gg] = (unsigned)((gg * 64 + w * 8 + (lane & 7)) * 512);

    const unsigned xw0 = (unsigned)(b0 & 7) * 16u;
    const unsigned xw1 = (unsigned)((b0 + 8) & 7) * 16u;
    const unsigned relH0 = (unsigned)b0 * 512u + (((unsigned)(2 * hg0)) ^ xw0);
    const unsigned relH1 = (unsigned)(b0 + 8) * 512u + (((unsigned)(2 * hg0)) ^ xw1);
    unsigned rmap[4];
#pragma unroll
    for (unsigned r = 0; r < 4; r++) rmap[r] = mapa_sh(sb, r);

    float2 xig[3][2];
    {
        const int t0 = dir ? (SEQL - 1) : 0;
        const float* xp0 = xi + ((size_t)(bg * 16 + b0) * SEQL + t0) * G3 + hg0;
        const float* xp1 = xi + ((size_t)(bg * 16 + b0 + 8) * SEQL + t0) * G3 + hg0;
#pragma unroll
        for (int gg = 0; gg < 3; gg++) {
            xig[gg][0] = *(const float2*)(xp0 + gg * HID);
            xig[gg][1] = *(const float2*)(xp1 + gg * HID);
        }
    }

    for (int s = 0; s < SEQL; s++) {
        const int t = dir ? (SEQL - 1 - s) : s;
        const unsigned rdb = RA_BASE + (unsigned)(s & 1) * 16384u;
        const unsigned wrb = RA_BASE + (unsigned)((s + 1) & 1) * 16384u;

        float acc[3][4];
#pragma unroll
        for (int gg = 0; gg < 3; gg++)
#pragma unroll
            for (int q = 0; q < 4; q++) acc[gg][q] = 0.f;

#pragma unroll
        for (int term = 0; term < 3; term++) {
            const unsigned Ab = sb + rdb + ((term == 1) ? 8192u : 0u);
            const unsigned Wb = sb + ((term == 2) ? RW_LO : RW_HI);
#pragma unroll
            for (int ks2 = 0; ks2 < 8; ks2++) {
                const unsigned k0b = (unsigned)(ks2 * 64);
                unsigned af0[4], af1[4];
                ldsm_x4(af0, Ab + arow_off + ((k0b + acol) ^ axor));
                ldsm_x4(af1, Ab + arow_off + ((k0b + 32u + acol) ^ axor));
#pragma unroll
                for (int gg = 0; gg < 3; gg++) {
                    unsigned bfr[4];
                    ldsm_x4(bfr, Wb + wrow_off[gg] + ((k0b + bcol) ^ bxor));
                    mma_bf16(acc[gg], af0, bfr);
                    mma_bf16(acc[gg], af1, bfr + 2);
                }
            }
        }

        float hp[2][2];
        {
            const __nv_bfloat162 h0w = *(const __nv_bfloat162*)(rsm + rdb + relH0);
            const __nv_bfloat162 l0w = *(const __nv_bfloat162*)(rsm + rdb + 8192u + relH0);
            const __nv_bfloat162 h1w = *(const __nv_bfloat162*)(rsm + rdb + relH1);
            const __nv_bfloat162 l1w = *(const __nv_bfloat162*)(rsm + rdb + 8192u + relH1);
            hp[0][0] = __bfloat162float(h0w.x) + __bfloat162float(l0w.x);
            hp[0][1] = __bfloat162float(h0w.y) + __bfloat162float(l0w.y);
            hp[1][0] = __bfloat162float(h1w.x) + __bfloat162float(l1w.x);
            hp[1][1] = __bfloat162float(h1w.y) + __bfloat162float(l1w.y);
        }

        float hnew[2][2];
#pragma unroll
        for (int bi = 0; bi < 2; bi++) {
#pragma unroll
            for (int hj = 0; hj < 2; hj++) {
                const int q = bi * 2 + hj;
                const float gr = acc[0][q] + (hj ? br2.y : br2.x);
                const float gz = acc[1][q] + (hj ? bz2.y : bz2.x);
                const float gn = acc[2][q] + (hj ? bn2.y : bn2.x);
                const float xr = hj ? xig[0][bi].y : xig[0][bi].x;
                const float xz = hj ? xig[1][bi].y : xig[1][bi].x;
                const float xn = hj ? xig[2][bi].y : xig[2][bi].x;
                const float rg = sigmoid_f(xr + gr);
                const float zg = sigmoid_f(xz + gz);
                const float ng = tanh_f(xn + rg * gn);
                hnew[bi][hj] = (1.f - zg) * ng + zg * hp[bi][hj];
            }
        }

        unsigned whw[2], wlw[2];
#pragma unroll
        for (int bi = 0; bi < 2; bi++) {
            const float r0 = __bfloat162float(__float2bfloat16(hnew[bi][0]));
            const float r1 = __bfloat162float(__float2bfloat16(hnew[bi][1]));
            whw[bi] = pack_bf16(hnew[bi][0], hnew[bi][1]);
            wlw[bi] = pack_bf16(hnew[bi][0] - r0, hnew[bi][1] - r1);
        }

#pragma unroll
        for (int bi = 0; bi < 2; bi++) {
            const int b = bg * 16 + b0 + bi * 8;
            const size_t row = (size_t)b * SEQL + t;
            if (layer) {
                *(float2*)(g_seq1 + row * 512 + zoff + hg0) =
                    make_float2(hnew[bi][0], hnew[bi][1]);
            } else {
                const float f0 = __half2float(__float2half_rn(hnew[bi][0]));
                const float f1 = __half2float(__float2half_rn(hnew[bi][1]));
                *(unsigned*)&g_a2[row * 1024 + zoff + hg0] =
                    pack_f16(hnew[bi][0], hnew[bi][1]);
                *(unsigned*)&g_a2[row * 1024 + 512 + zoff + hg0] =
                    pack_f16(hnew[bi][0] - f0, hnew[bi][1] - f1);
            }
        }

#pragma unroll
        for (unsigned r = 0; r < 4; r++) {
            st_cluster_u32(rmap[r] + wrb + relH0, whw[0]);
            st_cluster_u32(rmap[r] + wrb + 8192u + relH0, wlw[0]);
            st_cluster_u32(rmap[r] + wrb + relH1, whw[1]);
            st_cluster_u32(rmap[r] + wrb + 8192u + relH1, wlw[1]);
        }

        cluster_arrive();

        if (s + 1 < SEQL) {
            const int tn_ = dir ? (SEQL - 2 - s) : (s + 1);
            const float* xp0 = xi + ((size_t)(bg * 16 + b0) * SEQL + tn_) * G3 + hg0;
            const float* xp1 = xi + ((size_t)(bg * 16 + b0 + 8) * SEQL + tn_) * G3 + hg0;
#pragma unroll
            for (int gg = 0; gg < 3; gg++) {
                xig[gg][0] = *(const float2*)(xp0 + gg * HID);
                xig[gg][1] = *(const float2*)(xp1 + gg * HID);
            }
        }

        cluster_wait();
    }
}

// ---------------- heads: warp-per-row ------------------------------------------
__global__ __launch_bounds__(256) void fc_heads(
    const float* __restrict__ fc1w, const float* __restrict__ fc1b,
    const float* __restrict__ fc2w, const float* __restrict__ fc2b,
    float* __restrict__ y, float* __restrict__ y2)
{
    __shared__ float ws[11 * 512];
    __shared__ float bsh[11];
    const int tid = threadIdx.x;
    for (int i = tid; i < 5120; i += 256) ws[i] = fc2w[i];
    for (int i = tid; i < 512; i += 256) ws[5120 + i] = fc1w[i];
    if (tid < 10) bsh[tid] = fc2b[tid];
    if (tid == 10) bsh[10] = fc1b[0];
    __syncthreads();

    const int wid = tid >> 5, lane = tid & 31;
    const int bt = blockIdx.x * 8 + wid;
    const float4* row = (const float4*)(g_seq1 + (size_t)bt * 512);
    float4 v[4];
#pragma unroll
    for (int q = 0; q < 4; q++) v[q] = row[q * 32 + lane];

#pragma unroll
    for (int j = 0; j < 11; j++) {
        const float4* wj = (const float4*)(ws + j * 512);
        float s = 0.f;
#pragma unroll
        for (int q = 0; q < 4; q++) {
            const float4 wv = wj[q * 32 + lane];
            s += v[q].x * wv.x + v[q].y * wv.y + v[q].z * wv.z + v[q].w * wv.w;
        }
#pragma unroll
        for (int off = 16; off; off >>= 1) s += __shfl_xor_sync(0xffffffffu, s, off);
        if (lane == 0) {
            if (j < 10) y2[(size_t)bt * 10 + j] = s + bsh[j];
            else        y[bt] = s + bsh[10];
        }
    }
}

__global__ __launch_bounds__(256) void softmax_y_kernel(const float* __restrict__ y) {
    const int b = blockIdx.x;
    __shared__ float sh[256];
    const int tid = threadIdx.x;
    float v = (tid < SEQL) ? y[b * SEQL + tid] : -INFINITY;
    sh[tid] = v; __syncthreads();
    for (int s = 128; s; s >>= 1) {
        if (tid < s) sh[tid] = fmaxf(sh[tid], sh[tid + s]);
        __syncthreads();
    }
    const float mx = sh[0]; __syncthreads();
    const float e = (tid < SEQL) ? __expf(v - mx) : 0.f;
    sh[tid] = e; __syncthreads();
    for (int s = 128; s; s >>= 1) {
        if (tid < s) sh[tid] += sh[tid + s];
        __syncthreads();
    }
    const float inv = 1.f / sh[0];
    if (tid < SEQL) g_p[b * SEQL + tid] = e * inv * 0.1f;
}

__global__ __launch_bounds__(256) void softmax_y2_kernel(
    const float* __restrict__ y2, float* __restrict__ y3)
{
    const int b = blockIdx.x;
    const int tid = threadIdx.x;
    __shared__ float sh[256];
    const float* src = y2 + (size_t)b * 2000;
    float mx = -INFINITY;
    for (int i = tid; i < 2000; i += 256) mx = fmaxf(mx, src[i]);
    sh[tid] = mx; __syncthreads();
    for (int s = 128; s; s >>= 1) {
        if (tid < s) sh[tid] = fmaxf(sh[tid], sh[tid + s]);
        __syncthreads();
    }
    mx = sh[0]; __syncthreads();
    float sum = 0.f;
    for (int i = tid; i < 2000; i += 256) sum += __expf(src[i] - mx);
    sh[tid] = sum; __syncthreads();
    for (int s = 128; s; s >>= 1) {
        if (tid < s) sh[tid] += sh[tid + s];
        __syncthreads();
    }
    const float inv = 1.f / sh[0];
    for (int i = tid; i < 2000; i += 256)
        y3[(size_t)b * 2000 + i] = __expf(src[i] - mx) * inv + g_p[b * SEQL + i / 10];
}

// ---------------- driver ------------------------------------------------------
extern "C" void kernel_launch(void* const* d_in, const int* in_sizes, int n_in,
                              void* d_out, int out_size) {
    (void)in_sizes; (void)n_in; (void)out_size;
    const float* x        = (const float*)d_in[0];
    const float* w_ih_l0  = (const float*)d_in[1];
    const float* w_hh_l0  = (const float*)d_in[2];
    const float* b_ih_l0  = (const float*)d_in[3];
    const float* b_hh_l0  = (const float*)d_in[4];
    const float* w_ih_l0r = (const float*)d_in[5];
    const float* w_hh_l0r = (const float*)d_in[6];
    const float* b_ih_l0r = (const float*)d_in[7];
    const float* b_hh_l0r = (const float*)d_in[8];
    const float* w_ih_l1  = (const float*)d_in[9];
    const float* w_hh_l1  = (const float*)d_in[10];
    const float* b_ih_l1  = (const float*)d_in[11];
    const float* b_hh_l1  = (const float*)d_in[12];
    const float* w_ih_l1r = (const float*)d_in[13];
    const float* w_hh_l1r = (const float*)d_in[14];
    const float* b_ih_l1r = (const float*)d_in[15];
    const float* b_hh_l1r = (const float*)d_in[16];
    const float* fc1_w    = (const float*)d_in[17];
    const float* fc1_b    = (const float*)d_in[18];
    const float* fc2_w    = (const float*)d_in[19];
    const float* fc2_b    = (const float*)d_in[20];

    float* y  = (float*)d_out;
    float* y2 = y + BL;
    float* y3 = y2 + BL * 10;

    static int configured = 0;
    if (!configured) {
        cudaFuncSetAttribute(gru_cluster, cudaFuncAttributeMaxDynamicSharedMemorySize,
                             GRU_SMEM_BYTES);
        cudaFuncSetAttribute(gemm_mma, cudaFuncAttributeMaxDynamicSharedMemorySize,
                             GT_SMEM);
        configured = 1;
    }

    __half* a2p = nullptr;
    __half* w2p = nullptr;
    cudaGetSymbolAddress((void**)&a2p, g_a2);
    cudaGetSymbolAddress((void**)&w2p, g_w2);

    const int A_ELEM = BL * 512;
    const int W_ELEM = G3 * 512;

    // ---- layer 0 ----
    convert_split<<<A_ELEM / 1024, 256>>>(x, a2p, A_ELEM);
    convert_split<<<W_ELEM / 1024, 256>>>(w_ih_l0,  w2p,                     W_ELEM);
    convert_split<<<W_ELEM / 1024, 256>>>(w_ih_l0r, w2p + (size_t)G3 * 1024, W_ELEM);
    gemm_mma<<<(BL / 128) * 12, 256, GT_SMEM>>>(b_ih_l0, b_ih_l0r);
    gru_cluster<<<128, 256, GRU_SMEM_BYTES>>>(w_hh_l0, w_hh_l0r, b_hh_l0, b_hh_l0r, 0);
    // layer-0 recurrence wrote split-fp16 g_a2 directly (no convert needed)

    // ---- layer 1 ----
    convert_split<<<W_ELEM / 1024, 256>>>(w_ih_l1,  w2p,                     W_ELEM);
    convert_split<<<W_ELEM / 1024, 256>>>(w_ih_l1r, w2p + (size_t)G3 * 1024, W_ELEM);
    gemm_mma<<<(BL / 128) * 12, 256, GT_SMEM>>>(b_ih_l1, b_ih_l1r);
    gru_cluster<<<128, 256, GRU_SMEM_BYTES>>>(w_hh_l1, w_hh_l1r, b_hh_l1, b_hh_l1r, 1);

    // ---- heads ----
    fc_heads<<<BL / 8, 256>>>(fc1_w, fc1_b, fc2_w, fc2_b, y, y2);
    softmax_y_kernel<<<BATCH, 256>>>(y);
    softmax_y2_kernel<<<BATCH, 256>>>(y2, y3);
}